// round 4
// baseline (speedup 1.0000x reference)
#include <cuda_runtime.h>
#include <math.h>
#include <stdint.h>

// Problem constants
#define BATCH 8
#define SQ    1024
#define SK    1024
#define DM    512
#define NH    8

// ---------------- device scratch ----------------------------------------------
__device__ float g_Ql[BATCH * SQ * DM];
__device__ float g_Kl[BATCH * SK * DM];
__device__ float g_VWt[BATCH * DM * SK];     // (V @ Wc)^T per batch: [b][d][sk]
__device__ float g_att[BATCH * SQ * SK];
__device__ float g_WleT[DM * DM];
__device__ float g_WqT[DM * DM];
__device__ float g_WkT[DM * DM];
__device__ float g_WcT[DM * DM];
__device__ float g_bc[DM];

// ---------------- PTX helpers (sm_80+ features only; plain sm_103 target) ------
__device__ __forceinline__ uint32_t smem_u32(const void* p) {
    uint32_t a;
    asm("{ .reg .u64 t; cvta.to.shared.u64 t, %1; cvt.u32.u64 %0, t; }" : "=r"(a) : "l"(p));
    return a;
}

#define CP_ASYNC16(dst, src) \
    asm volatile("cp.async.cg.shared.global [%0], [%1], 16;" :: "r"(dst), "l"(src) : "memory")
#define CP_COMMIT() asm volatile("cp.async.commit_group;" ::: "memory")
#define CP_WAIT1()  asm volatile("cp.async.wait_group 1;" ::: "memory")
#define CP_WAIT0()  asm volatile("cp.async.wait_group 0;" ::: "memory")

__device__ __forceinline__ uint32_t f2tf32(float v) {
    uint32_t r;
    asm("cvt.rna.tf32.f32 %0, %1;" : "=r"(r) : "f"(v));
    return r;
}
__device__ __forceinline__ float round_tf32(float v) {
    return __uint_as_float(f2tf32(v));
}

__device__ __forceinline__ void mma_tf32(float* c, const uint32_t* a, const uint32_t* b) {
    asm volatile(
        "mma.sync.aligned.m16n8k8.row.col.f32.tf32.tf32.f32 "
        "{%0,%1,%2,%3}, {%4,%5,%6,%7}, {%8,%9}, {%0,%1,%2,%3};"
        : "+f"(c[0]), "+f"(c[1]), "+f"(c[2]), "+f"(c[3])
        : "r"(a[0]), "r"(a[1]), "r"(a[2]), "r"(a[3]), "r"(b[0]), "r"(b[1]));
}

// ================================================================================
// tf32 mma.sync GEMM: C[M,N] = A[M,K] @ B[N,K]^T
//   A row-major [M,K] (row stride = Kdim), B row-major [N,K] (row stride = Kdim)
// MODE 0: C += bias[n] (if bias); store rounded to tf32 if ROUND_OUT
// MODE 1: C = C*scale + mask[bz][n]*-1e9
// MODE 2: transposed store (rounded): out[b2][n][mloc], b2=m0/1024, mloc=m0%1024,
//         row stride ldT, batch stride foldT; +bias[n] if bias
// CVT_A: round A fragments at load (use when A is raw external fp32 data);
//        B fragments are ALWAYS consumed raw (producers pre-round to tf32).
// grid (N/128, M/128, batches), 256 threads
// ================================================================================
#define BM 128
#define BN 128
#define BK 32
#define LDT 36                                   // padded smem row stride (floats)
#define TILE_F (BM * LDT)
#define GEMM_SMEM (4 * TILE_F * 4)               // 73728 B

template <int MODE, int CVT_A, int ROUND_OUT>
__global__ void __launch_bounds__(256, 2) gemm_mma(
    const float* __restrict__ A, const float* __restrict__ B, float* __restrict__ C,
    int Kdim, long sA, long sB, long sC,
    const float* __restrict__ bias, const int* __restrict__ mask, float scale,
    int ldT, long foldT)
{
    extern __shared__ float smem[];
    float* As[2] = { smem,              smem + TILE_F };
    float* Bs[2] = { smem + 2 * TILE_F, smem + 3 * TILE_F };
    const uint32_t smb = smem_u32(smem);

    const int tid = threadIdx.x;
    const int lane = tid & 31, wid = tid >> 5;
    const int wm = wid >> 2, wn = wid & 3;       // 2 x 4 warps, warp tile 64x32
    const int m0 = blockIdx.y * BM, n0 = blockIdx.x * BN, bz = blockIdx.z;

    const float* Ag = A + (long)bz * sA;
    const float* Bg = B + (long)bz * sB;

    const int lrow[4] = { (tid + 0)   >> 3, (tid + 256) >> 3,
                          (tid + 512) >> 3, (tid + 768) >> 3 };
    const int lcol = (tid & 7) * 4;

    float acc[4][4][4];
#pragma unroll
    for (int i = 0; i < 4; i++)
#pragma unroll
        for (int j = 0; j < 4; j++)
#pragma unroll
            for (int r = 0; r < 4; r++) acc[i][j][r] = 0.f;

    const int NC = Kdim / BK;

    auto issue = [&](int c, int buf) {
        const long k0 = (long)c * BK;
#pragma unroll
        for (int i = 0; i < 4; i++) {
            uint32_t da = smb + (uint32_t)((buf * TILE_F + lrow[i] * LDT + lcol) * 4);
            CP_ASYNC16(da, Ag + (long)(m0 + lrow[i]) * Kdim + k0 + lcol);
        }
#pragma unroll
        for (int i = 0; i < 4; i++) {
            uint32_t db = smb + (uint32_t)(((2 + buf) * TILE_F + lrow[i] * LDT + lcol) * 4);
            CP_ASYNC16(db, Bg + (long)(n0 + lrow[i]) * Kdim + k0 + lcol);
        }
        CP_COMMIT();
    };

    issue(0, 0);

    for (int c = 0; c < NC; c++) {
        const int buf = c & 1;
        if (c + 1 < NC) { issue(c + 1, buf ^ 1); CP_WAIT1(); }
        else            { CP_WAIT0(); }
        __syncthreads();

        const float* Asb = As[buf];
        const float* Bsb = Bs[buf];
        const int ra = wm * 64 + (lane >> 2);
        const int rb = wn * 32 + (lane >> 2);

#pragma unroll
        for (int kk = 0; kk < 4; kk++) {
            const int kb = kk * 8 + (lane & 3);
            uint32_t af[4][4], bf[4][2];
#pragma unroll
            for (int mt = 0; mt < 4; mt++) {
                const float* p = Asb + (ra + mt * 16) * LDT + kb;
                if (CVT_A) {
                    af[mt][0] = f2tf32(p[0]);
                    af[mt][1] = f2tf32(p[8 * LDT]);
                    af[mt][2] = f2tf32(p[4]);
                    af[mt][3] = f2tf32(p[8 * LDT + 4]);
                } else {
                    af[mt][0] = __float_as_uint(p[0]);
                    af[mt][1] = __float_as_uint(p[8 * LDT]);
                    af[mt][2] = __float_as_uint(p[4]);
                    af[mt][3] = __float_as_uint(p[8 * LDT + 4]);
                }
            }
#pragma unroll
            for (int nt = 0; nt < 4; nt++) {
                const float* p = Bsb + (rb + nt * 8) * LDT + kb;
                bf[nt][0] = __float_as_uint(p[0]);
                bf[nt][1] = __float_as_uint(p[4]);
            }
#pragma unroll
            for (int mt = 0; mt < 4; mt++)
#pragma unroll
                for (int nt = 0; nt < 4; nt++)
                    mma_tf32(acc[mt][nt], af[mt], bf[nt]);
        }
        __syncthreads();
    }

    // ---- epilogue ----
    if (MODE == 2) {
        float* stage = smem;                     // [128][132] (n_local x m_local)
        __syncthreads();
#pragma unroll
        for (int mt = 0; mt < 4; mt++) {
            const int r0 = wm * 64 + mt * 16 + (lane >> 2);
#pragma unroll
            for (int nt = 0; nt < 4; nt++) {
                const int c0 = wn * 32 + nt * 8 + (lane & 3) * 2;
                stage[(c0    ) * 132 + r0    ] = acc[mt][nt][0];
                stage[(c0 + 1) * 132 + r0    ] = acc[mt][nt][1];
                stage[(c0    ) * 132 + r0 + 8] = acc[mt][nt][2];
                stage[(c0 + 1) * 132 + r0 + 8] = acc[mt][nt][3];
            }
        }
        __syncthreads();
        const int b2 = m0 >> 10, mloc = (m0 & 1023) + (tid & 31) * 4;
        const int rq = tid >> 5;
#pragma unroll
        for (int it = 0; it < 16; it++) {
            const int nr = rq + it * 8;
            float4 v = *(const float4*)&stage[nr * 132 + (tid & 31) * 4];
            const float bb = bias ? bias[n0 + nr] : 0.f;
            v.x = round_tf32(v.x + bb); v.y = round_tf32(v.y + bb);
            v.z = round_tf32(v.z + bb); v.w = round_tf32(v.w + bb);
            *(float4*)&C[(long)b2 * foldT + (long)(n0 + nr) * ldT + mloc] = v;
        }
        return;
    }

    float* Cg = C + (long)bz * sC;
#pragma unroll
    for (int mt = 0; mt < 4; mt++) {
        const int r0 = m0 + wm * 64 + mt * 16 + (lane >> 2);
#pragma unroll
        for (int nt = 0; nt < 4; nt++) {
            const int c0 = n0 + wn * 32 + nt * 8 + (lane & 3) * 2;
            float2 v0 = { acc[mt][nt][0], acc[mt][nt][1] };
            float2 v1 = { acc[mt][nt][2], acc[mt][nt][3] };
            if (MODE == 0) {
                if (bias) {
                    v0.x += bias[c0]; v0.y += bias[c0 + 1];
                    v1.x += bias[c0]; v1.y += bias[c0 + 1];
                }
                if (ROUND_OUT) {
                    v0.x = round_tf32(v0.x); v0.y = round_tf32(v0.y);
                    v1.x = round_tf32(v1.x); v1.y = round_tf32(v1.y);
                }
            } else { // MODE 1
                const int* mk = mask + (long)bz * SK;
                float p0 = mk[c0] ? -1e9f : 0.f, p1 = mk[c0 + 1] ? -1e9f : 0.f;
                v0.x = v0.x * scale + p0; v0.y = v0.y * scale + p1;
                v1.x = v1.x * scale + p0; v1.y = v1.y * scale + p1;
            }
            *(float2*)&Cg[(long)r0 * gridDim.x * BN + c0]       = v0;
            *(float2*)&Cg[(long)(r0 + 8) * gridDim.x * BN + c0] = v1;
        }
    }
}

// ================================================================================
// helper kernels
// ================================================================================
// transpose + round to tf32 (weights feed mma B operands raw)
__global__ void transpose512(const float* __restrict__ in, float* __restrict__ out) {
    __shared__ float t[32][33];
    int bx = blockIdx.x * 32, by = blockIdx.y * 32;
    for (int i = threadIdx.y; i < 32; i += 8)
        t[i][threadIdx.x] = in[(by + i) * DM + bx + threadIdx.x];
    __syncthreads();
    for (int i = threadIdx.y; i < 32; i += 8)
        out[(bx + i) * DM + by + threadIdx.x] = round_tf32(t[threadIdx.x][i]);
}

__global__ void wl_sumT_kernel(const float* __restrict__ Wl, float* __restrict__ WleT) {
    int i = blockIdx.x * blockDim.x + threadIdx.x;
    if (i >= DM * DM) return;
    int k = i >> 9, n = i & 511;
    float s = 0.f;
#pragma unroll
    for (int h = 0; h < NH; h++) s += Wl[((long)(h * DM + k)) * DM + n];
    WleT[n * DM + k] = round_tf32(s);
}

// bc[n] = bl[n] + sum_k bv[k] * WleT[n][k]
__global__ void bc_kernel(const float* __restrict__ bl, const float* __restrict__ bv,
                          const float* __restrict__ WleT, float* __restrict__ bc) {
    int n = blockIdx.x * blockDim.x + threadIdx.x;
    if (n >= DM) return;
    float s = bl[n];
    for (int k = 0; k < DM; k++) s += bv[k] * WleT[n * DM + k];
    bc[n] = s;
}

// fused softmax + 8-way head replication; one block per (q, b)
// writes tf32-rounded probs to att scratch (fed raw to final GEMM),
// full-precision probs to the att_ws output region.
__global__ void softmax_replicate(float* __restrict__ att, float* __restrict__ out_att) {
    const int q = blockIdx.x, b = blockIdx.y, t = threadIdx.x;
    float* row = att + ((long)(b * SQ + q)) * SK;
    float4 v = ((const float4*)row)[t];

    __shared__ float red[256];
    float m = fmaxf(fmaxf(v.x, v.y), fmaxf(v.z, v.w));
    red[t] = m;
    __syncthreads();
#pragma unroll
    for (int s = 128; s > 0; s >>= 1) {
        if (t < s) red[t] = fmaxf(red[t], red[t + s]);
        __syncthreads();
    }
    m = red[0];
    __syncthreads();

    float4 e;
    e.x = expf(v.x - m); e.y = expf(v.y - m);
    e.z = expf(v.z - m); e.w = expf(v.w - m);
    red[t] = e.x + e.y + e.z + e.w;
    __syncthreads();
#pragma unroll
    for (int s = 128; s > 0; s >>= 1) {
        if (t < s) red[t] += red[t + s];
        __syncthreads();
    }
    float inv = 1.0f / red[0];
    e.x *= inv; e.y *= inv; e.z *= inv; e.w *= inv;

    float4 er;
    er.x = round_tf32(e.x); er.y = round_tf32(e.y);
    er.z = round_tf32(e.z); er.w = round_tf32(e.w);
    ((float4*)row)[t] = er;

    if (out_att) {
#pragma unroll
        for (int h = 0; h < NH; h++)
            ((float4*)(out_att + (((long)(b * NH + h) * SQ) + q) * SK))[t] = e;
    }
}

// ================================================================================
// launch
// ================================================================================
extern "C" void kernel_launch(void* const* d_in, const int* in_sizes, int n_in,
                              void* d_out, int out_size) {
    const float* Q    = (const float*)d_in[0];
    const float* K    = (const float*)d_in[1];
    const float* V    = (const float*)d_in[2];
    const int*   mask = (const int*)  d_in[3];
    const float* Wq   = (const float*)d_in[4];
    const float* bq   = (const float*)d_in[5];
    const float* Wk   = (const float*)d_in[6];
    const float* bk   = (const float*)d_in[7];
    const float* Wv   = (const float*)d_in[8];
    const float* bv   = (const float*)d_in[9];
    const float* Wl   = (const float*)d_in[10];
    const float* bl   = (const float*)d_in[11];

    float *Ql, *Kl, *VWt, *att, *wleT, *wqT, *wkT, *wcT, *bc;
    cudaGetSymbolAddress((void**)&Ql,   g_Ql);
    cudaGetSymbolAddress((void**)&Kl,   g_Kl);
    cudaGetSymbolAddress((void**)&VWt,  g_VWt);
    cudaGetSymbolAddress((void**)&att,  g_att);
    cudaGetSymbolAddress((void**)&wleT, g_WleT);
    cudaGetSymbolAddress((void**)&wqT,  g_WqT);
    cudaGetSymbolAddress((void**)&wkT,  g_WkT);
    cudaGetSymbolAddress((void**)&wcT,  g_WcT);
    cudaGetSymbolAddress((void**)&bc,   g_bc);

    float* Yout = (float*)d_out;
    const long YSIZE = (long)BATCH * SQ * DM;
    const long ASIZE = (long)BATCH * NH * SQ * SK;
    float* out_att = ((long)out_size >= YSIZE + ASIZE) ? (Yout + YSIZE) : nullptr;
    const float inv_scale = 1.0f / sqrtf((float)DM);

    cudaFuncSetAttribute(gemm_mma<0,1,1>, cudaFuncAttributeMaxDynamicSharedMemorySize, GEMM_SMEM);
    cudaFuncSetAttribute(gemm_mma<0,0,0>, cudaFuncAttributeMaxDynamicSharedMemorySize, GEMM_SMEM);
    cudaFuncSetAttribute(gemm_mma<1,0,0>, cudaFuncAttributeMaxDynamicSharedMemorySize, GEMM_SMEM);
    cudaFuncSetAttribute(gemm_mma<2,1,0>, cudaFuncAttributeMaxDynamicSharedMemorySize, GEMM_SMEM);

    // weight prep
    transpose512<<<dim3(16, 16), dim3(32, 8)>>>(Wq, wqT);
    transpose512<<<dim3(16, 16), dim3(32, 8)>>>(Wk, wkT);
    wl_sumT_kernel<<<(DM * DM + 255) / 256, 256>>>(Wl, wleT);
    bc_kernel<<<2, 256>>>(bl, bv, wleT, bc);

    // WcT = (Wv @ Wle)^T  -- small GEMM, transposed store, ldT=512
    gemm_mma<2,1,0><<<dim3(DM / BN, DM / BM, 1), 256, GEMM_SMEM>>>(
        Wv, wleT, wcT, DM, 0, 0, 0, nullptr, nullptr, 0.f, DM, 0);

    // projections (outputs rounded to tf32 for downstream raw consumption)
    gemm_mma<0,1,1><<<dim3(DM / BN, (BATCH * SQ) / BM, 1), 256, GEMM_SMEM>>>(
        Q, wqT, Ql, DM, 0, 0, 0, bq, nullptr, 0.f, 0, 0);
    gemm_mma<0,1,1><<<dim3(DM / BN, (BATCH * SK) / BM, 1), 256, GEMM_SMEM>>>(
        K, wkT, Kl, DM, 0, 0, 0, bk, nullptr, 0.f, 0, 0);

    // VWt = (V @ Wc)^T per batch: transposed store ldT=SK, fold DM*SK
    gemm_mma<2,1,0><<<dim3(DM / BN, (BATCH * SK) / BM, 1), 256, GEMM_SMEM>>>(
        V, wcT, VWt, DM, 0, 0, 0, nullptr, nullptr, 0.f, SK, (long)DM * SK);

    // scores = Ql @ Kl^T * s + mask
    gemm_mma<1,0,0><<<dim3(SK / BN, SQ / BM, BATCH), 256, GEMM_SMEM>>>(
        Ql, Kl, att, DM, (long)SQ * DM, (long)SK * DM, (long)SQ * SK,
        nullptr, mask, inv_scale, 0, 0);

    // softmax + replicate into att_ws output region
    softmax_replicate<<<dim3(SQ, BATCH), 256>>>(att, out_att);

    // Y = att @ VW + bc   (B = VWt [DM][SK] K-major per batch)
    gemm_mma<0,0,0><<<dim3(DM / BN, SQ / BM, BATCH), 256, GEMM_SMEM>>>(
        att, VWt, Yout, SK, (long)SQ * SK, (long)DM * SK, (long)SQ * DM,
        bc, nullptr, 0.f, 0, 0);
}

// round 5
// speedup vs baseline: 1.1841x; 1.1841x over previous
#include <cuda_runtime.h>
#include <math.h>
#include <stdint.h>

// Problem constants
#define BATCH 8
#define SQ    1024
#define SK    1024
#define DM    512
#define NH    8

// ---------------- device scratch ----------------------------------------------
__device__ float g_Ql[BATCH * SQ * DM];
__device__ float g_Kl[BATCH * SK * DM];
__device__ float g_VWt[BATCH * DM * SK];     // (V @ Wc)^T per batch: [b][d][sk]
__device__ float g_att[BATCH * SQ * SK];
__device__ float g_WleT[DM * DM];
__device__ float g_WqT[DM * DM];
__device__ float g_WkT[DM * DM];
__device__ float g_WcT[DM * DM];
__device__ float g_bc[DM];

// ---------------- PTX helpers (sm_80+ features only; plain sm_103 target) ------
__device__ __forceinline__ uint32_t smem_u32(const void* p) {
    uint32_t a;
    asm("{ .reg .u64 t; cvta.to.shared.u64 t, %1; cvt.u32.u64 %0, t; }" : "=r"(a) : "l"(p));
    return a;
}

#define CP_ASYNC16(dst, src) \
    asm volatile("cp.async.cg.shared.global [%0], [%1], 16;" :: "r"(dst), "l"(src) : "memory")
#define CP_COMMIT() asm volatile("cp.async.commit_group;" ::: "memory")
#define CP_WAIT1()  asm volatile("cp.async.wait_group 1;" ::: "memory")
#define CP_WAIT0()  asm volatile("cp.async.wait_group 0;" ::: "memory")

__device__ __forceinline__ uint32_t f2tf32(float v) {
    uint32_t r;
    asm("cvt.rna.tf32.f32 %0, %1;" : "=r"(r) : "f"(v));
    return r;
}
__device__ __forceinline__ float round_tf32(float v) {
    return __uint_as_float(f2tf32(v));
}

__device__ __forceinline__ void mma_tf32(float* c, const uint32_t* a, const uint32_t* b) {
    asm volatile(
        "mma.sync.aligned.m16n8k8.row.col.f32.tf32.tf32.f32 "
        "{%0,%1,%2,%3}, {%4,%5,%6,%7}, {%8,%9}, {%0,%1,%2,%3};"
        : "+f"(c[0]), "+f"(c[1]), "+f"(c[2]), "+f"(c[3])
        : "r"(a[0]), "r"(a[1]), "r"(a[2]), "r"(a[3]), "r"(b[0]), "r"(b[1]));
}

// ================================================================================
// tf32 mma.sync GEMM: C[M,N] = A[M,K] @ B[N,K]^T
// MODE 0: C += bias[n] (if bias); store rounded to tf32 if ROUND_OUT
// MODE 1: C = C*scale + mask[bz][n]*-1e9
// MODE 2: transposed store (rounded): out[b2][n][mloc], b2=m0/1024, mloc=m0%1024
// CVT_A: round A fragments at load (A is raw external fp32); B always raw
// grid (N/128, M/128, batches), 256 threads
// ================================================================================
#define BM 128
#define BN 128
#define BK 32
#define LDT 36
#define TILE_F (BM * LDT)
#define GEMM_SMEM (4 * TILE_F * 4)               // 73728 B

template <int MODE, int CVT_A, int ROUND_OUT>
__global__ void __launch_bounds__(256, 2) gemm_mma(
    const float* __restrict__ A, const float* __restrict__ B, float* __restrict__ C,
    int Kdim, long sA, long sB, long sC,
    const float* __restrict__ bias, const int* __restrict__ mask, float scale,
    int ldT, long foldT)
{
    extern __shared__ float smem[];
    float* As[2] = { smem,              smem + TILE_F };
    float* Bs[2] = { smem + 2 * TILE_F, smem + 3 * TILE_F };
    const uint32_t smb = smem_u32(smem);

    const int tid = threadIdx.x;
    const int lane = tid & 31, wid = tid >> 5;
    const int wm = wid >> 2, wn = wid & 3;       // 2 x 4 warps, warp tile 64x32
    const int m0 = blockIdx.y * BM, n0 = blockIdx.x * BN, bz = blockIdx.z;

    const float* Ag = A + (long)bz * sA;
    const float* Bg = B + (long)bz * sB;

    const int lrow[4] = { (tid + 0)   >> 3, (tid + 256) >> 3,
                          (tid + 512) >> 3, (tid + 768) >> 3 };
    const int lcol = (tid & 7) * 4;

    float acc[4][4][4];
#pragma unroll
    for (int i = 0; i < 4; i++)
#pragma unroll
        for (int j = 0; j < 4; j++)
#pragma unroll
            for (int r = 0; r < 4; r++) acc[i][j][r] = 0.f;

    const int NC = Kdim / BK;

    auto issue = [&](int c, int buf) {
        const long k0 = (long)c * BK;
#pragma unroll
        for (int i = 0; i < 4; i++) {
            uint32_t da = smb + (uint32_t)((buf * TILE_F + lrow[i] * LDT + lcol) * 4);
            CP_ASYNC16(da, Ag + (long)(m0 + lrow[i]) * Kdim + k0 + lcol);
        }
#pragma unroll
        for (int i = 0; i < 4; i++) {
            uint32_t db = smb + (uint32_t)(((2 + buf) * TILE_F + lrow[i] * LDT + lcol) * 4);
            CP_ASYNC16(db, Bg + (long)(n0 + lrow[i]) * Kdim + k0 + lcol);
        }
        CP_COMMIT();
    };

    issue(0, 0);

    for (int c = 0; c < NC; c++) {
        const int buf = c & 1;
        if (c + 1 < NC) { issue(c + 1, buf ^ 1); CP_WAIT1(); }
        else            { CP_WAIT0(); }
        __syncthreads();

        const float* Asb = As[buf];
        const float* Bsb = Bs[buf];
        const int ra = wm * 64 + (lane >> 2);
        const int rb = wn * 32 + (lane >> 2);

#pragma unroll
        for (int kk = 0; kk < 4; kk++) {
            const int kb = kk * 8 + (lane & 3);
            uint32_t af[4][4], bf[4][2];
#pragma unroll
            for (int mt = 0; mt < 4; mt++) {
                const float* p = Asb + (ra + mt * 16) * LDT + kb;
                if (CVT_A) {
                    af[mt][0] = f2tf32(p[0]);
                    af[mt][1] = f2tf32(p[8 * LDT]);
                    af[mt][2] = f2tf32(p[4]);
                    af[mt][3] = f2tf32(p[8 * LDT + 4]);
                } else {
                    af[mt][0] = __float_as_uint(p[0]);
                    af[mt][1] = __float_as_uint(p[8 * LDT]);
                    af[mt][2] = __float_as_uint(p[4]);
                    af[mt][3] = __float_as_uint(p[8 * LDT + 4]);
                }
            }
#pragma unroll
            for (int nt = 0; nt < 4; nt++) {
                const float* p = Bsb + (rb + nt * 8) * LDT + kb;
                bf[nt][0] = __float_as_uint(p[0]);
                bf[nt][1] = __float_as_uint(p[4]);
            }
#pragma unroll
            for (int mt = 0; mt < 4; mt++)
#pragma unroll
                for (int nt = 0; nt < 4; nt++)
                    mma_tf32(acc[mt][nt], af[mt], bf[nt]);
        }
        __syncthreads();
    }

    // ---- epilogue ----
    if (MODE == 2) {
        float* stage = smem;                     // [128][132] (n_local x m_local)
        __syncthreads();
#pragma unroll
        for (int mt = 0; mt < 4; mt++) {
            const int r0 = wm * 64 + mt * 16 + (lane >> 2);
#pragma unroll
            for (int nt = 0; nt < 4; nt++) {
                const int c0 = wn * 32 + nt * 8 + (lane & 3) * 2;
                stage[(c0    ) * 132 + r0    ] = acc[mt][nt][0];
                stage[(c0 + 1) * 132 + r0    ] = acc[mt][nt][1];
                stage[(c0    ) * 132 + r0 + 8] = acc[mt][nt][2];
                stage[(c0 + 1) * 132 + r0 + 8] = acc[mt][nt][3];
            }
        }
        __syncthreads();
        const int b2 = m0 >> 10, mloc = (m0 & 1023) + (tid & 31) * 4;
        const int rq = tid >> 5;
#pragma unroll
        for (int it = 0; it < 16; it++) {
            const int nr = rq + it * 8;
            float4 v = *(const float4*)&stage[nr * 132 + (tid & 31) * 4];
            const float bb = bias ? bias[n0 + nr] : 0.f;
            v.x = round_tf32(v.x + bb); v.y = round_tf32(v.y + bb);
            v.z = round_tf32(v.z + bb); v.w = round_tf32(v.w + bb);
            *(float4*)&C[(long)b2 * foldT + (long)(n0 + nr) * ldT + mloc] = v;
        }
        return;
    }

    float* Cg = C + (long)bz * sC;
#pragma unroll
    for (int mt = 0; mt < 4; mt++) {
        const int r0 = m0 + wm * 64 + mt * 16 + (lane >> 2);
#pragma unroll
        for (int nt = 0; nt < 4; nt++) {
            const int c0 = n0 + wn * 32 + nt * 8 + (lane & 3) * 2;
            float2 v0 = { acc[mt][nt][0], acc[mt][nt][1] };
            float2 v1 = { acc[mt][nt][2], acc[mt][nt][3] };
            if (MODE == 0) {
                if (bias) {
                    v0.x += bias[c0]; v0.y += bias[c0 + 1];
                    v1.x += bias[c0]; v1.y += bias[c0 + 1];
                }
                if (ROUND_OUT) {
                    v0.x = round_tf32(v0.x); v0.y = round_tf32(v0.y);
                    v1.x = round_tf32(v1.x); v1.y = round_tf32(v1.y);
                }
            } else { // MODE 1
                const int* mk = mask + (long)bz * SK;
                float p0 = mk[c0] ? -1e9f : 0.f, p1 = mk[c0 + 1] ? -1e9f : 0.f;
                v0.x = v0.x * scale + p0; v0.y = v0.y * scale + p1;
                v1.x = v1.x * scale + p0; v1.y = v1.y * scale + p1;
            }
            *(float2*)&Cg[(long)r0 * gridDim.x * BN + c0]       = v0;
            *(float2*)&Cg[(long)(r0 + 8) * gridDim.x * BN + c0] = v1;
        }
    }
}

// ================================================================================
// helper kernels
// ================================================================================
// fused dual transpose + round to tf32; z selects which weight
__global__ void transpose512_2(const float* __restrict__ w0, float* __restrict__ o0,
                               const float* __restrict__ w1, float* __restrict__ o1) {
    __shared__ float t[32][33];
    const float* in  = blockIdx.z ? w1 : w0;
    float*       out = blockIdx.z ? o1 : o0;
    int bx = blockIdx.x * 32, by = blockIdx.y * 32;
    for (int i = threadIdx.y; i < 32; i += 8)
        t[i][threadIdx.x] = in[(by + i) * DM + bx + threadIdx.x];
    __syncthreads();
    for (int i = threadIdx.y; i < 32; i += 8)
        out[(bx + i) * DM + by + threadIdx.x] = round_tf32(t[threadIdx.x][i]);
}

__global__ void wl_sumT_kernel(const float* __restrict__ Wl, float* __restrict__ WleT) {
    int i = blockIdx.x * blockDim.x + threadIdx.x;
    if (i >= DM * DM) return;
    int k = i >> 9, n = i & 511;
    float s = 0.f;
#pragma unroll
    for (int h = 0; h < NH; h++) s += Wl[((long)(h * DM + k)) * DM + n];
    WleT[n * DM + k] = round_tf32(s);
}

// bc[n] = bl[n] + sum_k bv[k] * WleT[n][k]  -- one block per n, tree reduction
__global__ void bc_kernel(const float* __restrict__ bl, const float* __restrict__ bv,
                          const float* __restrict__ WleT, float* __restrict__ bc) {
    const int n = blockIdx.x, t = threadIdx.x;
    __shared__ float red[256];
    float s = 0.f;
    for (int k = t; k < DM; k += 256) s += bv[k] * WleT[n * DM + k];
    red[t] = s;
    __syncthreads();
#pragma unroll
    for (int o = 128; o >= 32; o >>= 1) {
        if (t < o) red[t] += red[t + o];
        __syncthreads();
    }
    if (t < 32) {
        float v = red[t];
#pragma unroll
        for (int o = 16; o > 0; o >>= 1)
            v += __shfl_down_sync(0xffffffffu, v, o);
        if (t == 0) bc[n] = bl[n] + v;
    }
}

// fused softmax + 8-way head replication; one block per (q, b)
__global__ void softmax_replicate(float* __restrict__ att, float* __restrict__ out_att) {
    const int q = blockIdx.x, b = blockIdx.y, t = threadIdx.x;
    float* row = att + ((long)(b * SQ + q)) * SK;
    float4 v = ((const float4*)row)[t];

    __shared__ float red[256];
    float m = fmaxf(fmaxf(v.x, v.y), fmaxf(v.z, v.w));
    red[t] = m;
    __syncthreads();
#pragma unroll
    for (int s = 128; s > 0; s >>= 1) {
        if (t < s) red[t] = fmaxf(red[t], red[t + s]);
        __syncthreads();
    }
    m = red[0];
    __syncthreads();

    float4 e;
    e.x = expf(v.x - m); e.y = expf(v.y - m);
    e.z = expf(v.z - m); e.w = expf(v.w - m);
    red[t] = e.x + e.y + e.z + e.w;
    __syncthreads();
#pragma unroll
    for (int s = 128; s > 0; s >>= 1) {
        if (t < s) red[t] += red[t + s];
        __syncthreads();
    }
    float inv = 1.0f / red[0];
    e.x *= inv; e.y *= inv; e.z *= inv; e.w *= inv;

    float4 er;
    er.x = round_tf32(e.x); er.y = round_tf32(e.y);
    er.z = round_tf32(e.z); er.w = round_tf32(e.w);
    ((float4*)row)[t] = er;

    if (out_att) {
#pragma unroll
        for (int h = 0; h < NH; h++)
            ((float4*)(out_att + (((long)(b * NH + h) * SQ) + q) * SK))[t] = e;
    }
}

// ================================================================================
// launch
// ================================================================================
extern "C" void kernel_launch(void* const* d_in, const int* in_sizes, int n_in,
                              void* d_out, int out_size) {
    const float* Q    = (const float*)d_in[0];
    const float* K    = (const float*)d_in[1];
    const float* V    = (const float*)d_in[2];
    const int*   mask = (const int*)  d_in[3];
    const float* Wq   = (const float*)d_in[4];
    const float* bq   = (const float*)d_in[5];
    const float* Wk   = (const float*)d_in[6];
    const float* bk   = (const float*)d_in[7];
    const float* Wv   = (const float*)d_in[8];
    const float* bv   = (const float*)d_in[9];
    const float* Wl   = (const float*)d_in[10];
    const float* bl   = (const float*)d_in[11];

    float *Ql, *Kl, *VWt, *att, *wleT, *wqT, *wkT, *wcT, *bc;
    cudaGetSymbolAddress((void**)&Ql,   g_Ql);
    cudaGetSymbolAddress((void**)&Kl,   g_Kl);
    cudaGetSymbolAddress((void**)&VWt,  g_VWt);
    cudaGetSymbolAddress((void**)&att,  g_att);
    cudaGetSymbolAddress((void**)&wleT, g_WleT);
    cudaGetSymbolAddress((void**)&wqT,  g_WqT);
    cudaGetSymbolAddress((void**)&wkT,  g_WkT);
    cudaGetSymbolAddress((void**)&wcT,  g_WcT);
    cudaGetSymbolAddress((void**)&bc,   g_bc);

    float* Yout = (float*)d_out;
    const long YSIZE = (long)BATCH * SQ * DM;
    const long ASIZE = (long)BATCH * NH * SQ * SK;
    float* out_att = ((long)out_size >= YSIZE + ASIZE) ? (Yout + YSIZE) : nullptr;
    const float inv_scale = 1.0f / sqrtf((float)DM);

    cudaFuncSetAttribute(gemm_mma<0,1,1>, cudaFuncAttributeMaxDynamicSharedMemorySize, GEMM_SMEM);
    cudaFuncSetAttribute(gemm_mma<0,0,0>, cudaFuncAttributeMaxDynamicSharedMemorySize, GEMM_SMEM);
    cudaFuncSetAttribute(gemm_mma<1,0,0>, cudaFuncAttributeMaxDynamicSharedMemorySize, GEMM_SMEM);
    cudaFuncSetAttribute(gemm_mma<2,1,0>, cudaFuncAttributeMaxDynamicSharedMemorySize, GEMM_SMEM);

    // weight prep
    transpose512_2<<<dim3(16, 16, 2), dim3(32, 8)>>>(Wq, wqT, Wk, wkT);
    wl_sumT_kernel<<<(DM * DM + 255) / 256, 256>>>(Wl, wleT);
    bc_kernel<<<DM, 256>>>(bl, bv, wleT, bc);

    // WcT = (Wv @ Wle)^T  -- small GEMM, transposed store, ldT=512
    gemm_mma<2,1,0><<<dim3(DM / BN, DM / BM, 1), 256, GEMM_SMEM>>>(
        Wv, wleT, wcT, DM, 0, 0, 0, nullptr, nullptr, 0.f, DM, 0);

    // projections (outputs rounded to tf32 for downstream raw consumption)
    gemm_mma<0,1,1><<<dim3(DM / BN, (BATCH * SQ) / BM, 1), 256, GEMM_SMEM>>>(
        Q, wqT, Ql, DM, 0, 0, 0, bq, nullptr, 0.f, 0, 0);
    gemm_mma<0,1,1><<<dim3(DM / BN, (BATCH * SK) / BM, 1), 256, GEMM_SMEM>>>(
        K, wkT, Kl, DM, 0, 0, 0, bk, nullptr, 0.f, 0, 0);

    // VWt = (V @ Wc)^T per batch: transposed store ldT=SK, fold DM*SK
    gemm_mma<2,1,0><<<dim3(DM / BN, (BATCH * SK) / BM, 1), 256, GEMM_SMEM>>>(
        V, wcT, VWt, DM, 0, 0, 0, nullptr, nullptr, 0.f, SK, (long)DM * SK);

    // scores = Ql @ Kl^T * s + mask
    gemm_mma<1,0,0><<<dim3(SK / BN, SQ / BM, BATCH), 256, GEMM_SMEM>>>(
        Ql, Kl, att, DM, (long)SQ * DM, (long)SK * DM, (long)SQ * SK,
        nullptr, mask, inv_scale, 0, 0);

    // softmax + replicate into att_ws output region
    softmax_replicate<<<dim3(SQ, BATCH), 256>>>(att, out_att);

    // Y = att @ VW + bc   (B = VWt [DM][SK] K-major per batch)
    gemm_mma<0,0,0><<<dim3(DM / BN, SQ / BM, BATCH), 256, GEMM_SMEM>>>(
        att, VWt, Yout, SK, (long)SQ * SK, (long)DM * SK, (long)SQ * DM,
        bc, nullptr, 0.f, 0, 0);
}

// round 6
// speedup vs baseline: 1.2175x; 1.0282x over previous
#include <cuda_runtime.h>
#include <math.h>
#include <stdint.h>

// Problem constants
#define BATCH 8
#define SQ    1024
#define SK    1024
#define DM    512
#define NH    8

// ---------------- device scratch ----------------------------------------------
__device__ float g_Ql[BATCH * SQ * DM];
__device__ float g_Kl[BATCH * SK * DM];
__device__ float g_VWt[BATCH * DM * SK];     // (V @ Wc)^T per batch: [b][d][sk]
__device__ float g_att[BATCH * SQ * SK];
__device__ float g_WleT[DM * DM];
__device__ float g_WqT[DM * DM];
__device__ float g_WkT[DM * DM];
__device__ float g_WcT[DM * DM];
__device__ float g_WcP[4 * DM * DM];         // split-K partials for WcT
__device__ float g_bc[DM];

// ---------------- PTX helpers (sm_80+ features only; plain sm_103 target) ------
__device__ __forceinline__ uint32_t smem_u32(const void* p) {
    uint32_t a;
    asm("{ .reg .u64 t; cvta.to.shared.u64 t, %1; cvt.u32.u64 %0, t; }" : "=r"(a) : "l"(p));
    return a;
}

#define CP_ASYNC16(dst, src) \
    asm volatile("cp.async.cg.shared.global [%0], [%1], 16;" :: "r"(dst), "l"(src) : "memory")
#define CP_COMMIT() asm volatile("cp.async.commit_group;" ::: "memory")
#define CP_WAIT1()  asm volatile("cp.async.wait_group 1;" ::: "memory")
#define CP_WAIT0()  asm volatile("cp.async.wait_group 0;" ::: "memory")

__device__ __forceinline__ uint32_t f2tf32(float v) {
    uint32_t r;
    asm("cvt.rna.tf32.f32 %0, %1;" : "=r"(r) : "f"(v));
    return r;
}
__device__ __forceinline__ float round_tf32(float v) {
    return __uint_as_float(f2tf32(v));
}

__device__ __forceinline__ void mma_tf32(float* c, const uint32_t* a, const uint32_t* b) {
    asm volatile(
        "mma.sync.aligned.m16n8k8.row.col.f32.tf32.tf32.f32 "
        "{%0,%1,%2,%3}, {%4,%5,%6,%7}, {%8,%9}, {%0,%1,%2,%3};"
        : "+f"(c[0]), "+f"(c[1]), "+f"(c[2]), "+f"(c[3])
        : "r"(a[0]), "r"(a[1]), "r"(a[2]), "r"(a[3]), "r"(b[0]), "r"(b[1]));
}

// ================================================================================
// tf32 mma.sync GEMM: C[M,N] = A[M,K(chunk)] @ B[N,K(chunk)]^T
//   A rows stride lda, B rows stride ldb; bz offsets A by sA, B by sB (elements)
// MODE 0: C += bias[n] (if bias); store rounded to tf32 if ROUND_OUT
// MODE 1: C = C*scale + mask[bz][n]*-1e9
// MODE 2: transposed store (rounded): base C + bz*sC; out[b2*foldT + n*ldT + mloc],
//         b2=m0/1024, mloc=m0%1024; +bias[n] if bias
// CVT_A: round A fragments at load (A is raw external fp32); B always raw
// grid (N/128, M/128, batches-or-ksplits), 256 threads
// ================================================================================
#define BM 128
#define BN 128
#define BK 32
#define LDT 36
#define TILE_F (BM * LDT)
#define GEMM_SMEM (4 * TILE_F * 4)               // 73728 B

template <int MODE, int CVT_A, int ROUND_OUT>
__global__ void __launch_bounds__(256, 2) gemm_mma(
    const float* __restrict__ A, const float* __restrict__ B, float* __restrict__ C,
    int Kdim, long sA, long sB, long sC,
    const float* __restrict__ bias, const int* __restrict__ mask, float scale,
    int ldT, long foldT, int lda, int ldb)
{
    extern __shared__ float smem[];
    float* As[2] = { smem,              smem + TILE_F };
    float* Bs[2] = { smem + 2 * TILE_F, smem + 3 * TILE_F };
    const uint32_t smb = smem_u32(smem);

    const int tid = threadIdx.x;
    const int lane = tid & 31, wid = tid >> 5;
    const int wm = wid >> 2, wn = wid & 3;       // 2 x 4 warps, warp tile 64x32
    const int m0 = blockIdx.y * BM, n0 = blockIdx.x * BN, bz = blockIdx.z;

    const float* Ag = A + (long)bz * sA;
    const float* Bg = B + (long)bz * sB;

    const int lrow[4] = { (tid + 0)   >> 3, (tid + 256) >> 3,
                          (tid + 512) >> 3, (tid + 768) >> 3 };
    const int lcol = (tid & 7) * 4;

    float acc[4][4][4];
#pragma unroll
    for (int i = 0; i < 4; i++)
#pragma unroll
        for (int j = 0; j < 4; j++)
#pragma unroll
            for (int r = 0; r < 4; r++) acc[i][j][r] = 0.f;

    const int NC = Kdim / BK;

    auto issue = [&](int c, int buf) {
        const long k0 = (long)c * BK;
#pragma unroll
        for (int i = 0; i < 4; i++) {
            uint32_t da = smb + (uint32_t)((buf * TILE_F + lrow[i] * LDT + lcol) * 4);
            CP_ASYNC16(da, Ag + (long)(m0 + lrow[i]) * lda + k0 + lcol);
        }
#pragma unroll
        for (int i = 0; i < 4; i++) {
            uint32_t db = smb + (uint32_t)(((2 + buf) * TILE_F + lrow[i] * LDT + lcol) * 4);
            CP_ASYNC16(db, Bg + (long)(n0 + lrow[i]) * ldb + k0 + lcol);
        }
        CP_COMMIT();
    };

    issue(0, 0);

    for (int c = 0; c < NC; c++) {
        const int buf = c & 1;
        if (c + 1 < NC) { issue(c + 1, buf ^ 1); CP_WAIT1(); }
        else            { CP_WAIT0(); }
        __syncthreads();

        const float* Asb = As[buf];
        const float* Bsb = Bs[buf];
        const int ra = wm * 64 + (lane >> 2);
        const int rb = wn * 32 + (lane >> 2);

#pragma unroll
        for (int kk = 0; kk < 4; kk++) {
            const int kb = kk * 8 + (lane & 3);
            uint32_t af[4][4], bf[4][2];
#pragma unroll
            for (int mt = 0; mt < 4; mt++) {
                const float* p = Asb + (ra + mt * 16) * LDT + kb;
                if (CVT_A) {
                    af[mt][0] = f2tf32(p[0]);
                    af[mt][1] = f2tf32(p[8 * LDT]);
                    af[mt][2] = f2tf32(p[4]);
                    af[mt][3] = f2tf32(p[8 * LDT + 4]);
                } else {
                    af[mt][0] = __float_as_uint(p[0]);
                    af[mt][1] = __float_as_uint(p[8 * LDT]);
                    af[mt][2] = __float_as_uint(p[4]);
                    af[mt][3] = __float_as_uint(p[8 * LDT + 4]);
                }
            }
#pragma unroll
            for (int nt = 0; nt < 4; nt++) {
                const float* p = Bsb + (rb + nt * 8) * LDT + kb;
                bf[nt][0] = __float_as_uint(p[0]);
                bf[nt][1] = __float_as_uint(p[4]);
            }
#pragma unroll
            for (int mt = 0; mt < 4; mt++)
#pragma unroll
                for (int nt = 0; nt < 4; nt++)
                    mma_tf32(acc[mt][nt], af[mt], bf[nt]);
        }
        __syncthreads();
    }

    // ---- epilogue ----
    if (MODE == 2) {
        float* Cz = C + (long)bz * sC;
        float* stage = smem;                     // [128][132] (n_local x m_local)
        __syncthreads();
#pragma unroll
        for (int mt = 0; mt < 4; mt++) {
            const int r0 = wm * 64 + mt * 16 + (lane >> 2);
#pragma unroll
            for (int nt = 0; nt < 4; nt++) {
                const int c0 = wn * 32 + nt * 8 + (lane & 3) * 2;
                stage[(c0    ) * 132 + r0    ] = acc[mt][nt][0];
                stage[(c0 + 1) * 132 + r0    ] = acc[mt][nt][1];
                stage[(c0    ) * 132 + r0 + 8] = acc[mt][nt][2];
                stage[(c0 + 1) * 132 + r0 + 8] = acc[mt][nt][3];
            }
        }
        __syncthreads();
        const int b2 = m0 >> 10, mloc = (m0 & 1023) + (tid & 31) * 4;
        const int rq = tid >> 5;
#pragma unroll
        for (int it = 0; it < 16; it++) {
            const int nr = rq + it * 8;
            float4 v = *(const float4*)&stage[nr * 132 + (tid & 31) * 4];
            const float bb = bias ? bias[n0 + nr] : 0.f;
            v.x = round_tf32(v.x + bb); v.y = round_tf32(v.y + bb);
            v.z = round_tf32(v.z + bb); v.w = round_tf32(v.w + bb);
            *(float4*)&Cz[(long)b2 * foldT + (long)(n0 + nr) * ldT + mloc] = v;
        }
        return;
    }

    float* Cg = C + (long)bz * sC;
#pragma unroll
    for (int mt = 0; mt < 4; mt++) {
        const int r0 = m0 + wm * 64 + mt * 16 + (lane >> 2);
#pragma unroll
        for (int nt = 0; nt < 4; nt++) {
            const int c0 = n0 + wn * 32 + nt * 8 + (lane & 3) * 2;
            float2 v0 = { acc[mt][nt][0], acc[mt][nt][1] };
            float2 v1 = { acc[mt][nt][2], acc[mt][nt][3] };
            if (MODE == 0) {
                if (bias) {
                    v0.x += bias[c0]; v0.y += bias[c0 + 1];
                    v1.x += bias[c0]; v1.y += bias[c0 + 1];
                }
                if (ROUND_OUT) {
                    v0.x = round_tf32(v0.x); v0.y = round_tf32(v0.y);
                    v1.x = round_tf32(v1.x); v1.y = round_tf32(v1.y);
                }
            } else { // MODE 1
                const int* mk = mask + (long)bz * SK;
                float p0 = mk[c0] ? -1e9f : 0.f, p1 = mk[c0 + 1] ? -1e9f : 0.f;
                v0.x = v0.x * scale + p0; v0.y = v0.y * scale + p1;
                v1.x = v1.x * scale + p0; v1.y = v1.y * scale + p1;
            }
            *(float2*)&Cg[(long)r0 * gridDim.x * BN + c0]       = v0;
            *(float2*)&Cg[(long)(r0 + 8) * gridDim.x * BN + c0] = v1;
        }
    }
}

// ================================================================================
// helper kernels
// ================================================================================
// fused dual transpose + round to tf32; z selects which weight
__global__ void transpose512_2(const float* __restrict__ w0, float* __restrict__ o0,
                               const float* __restrict__ w1, float* __restrict__ o1) {
    __shared__ float t[32][33];
    const float* in  = blockIdx.z ? w1 : w0;
    float*       out = blockIdx.z ? o1 : o0;
    int bx = blockIdx.x * 32, by = blockIdx.y * 32;
    for (int i = threadIdx.y; i < 32; i += 8)
        t[i][threadIdx.x] = in[(by + i) * DM + bx + threadIdx.x];
    __syncthreads();
    for (int i = threadIdx.y; i < 32; i += 8)
        out[(bx + i) * DM + by + threadIdx.x] = round_tf32(t[threadIdx.x][i]);
}

// WleT[n][k] = round_tf32(sum_h Wl[h*DM+k][n]) — tiled, coalesced both directions
__global__ void wl_sumT_tiled(const float* __restrict__ Wl, float* __restrict__ WleT) {
    __shared__ float t[32][33];
    int bx = blockIdx.x * 32, by = blockIdx.y * 32;   // bx: n, by: k
    for (int i = threadIdx.y; i < 32; i += 8) {
        float s = 0.f;
#pragma unroll
        for (int h = 0; h < NH; h++)
            s += Wl[((long)(h * DM) + by + i) * DM + bx + threadIdx.x];
        t[i][threadIdx.x] = s;
    }
    __syncthreads();
    for (int i = threadIdx.y; i < 32; i += 8)
        WleT[(bx + i) * DM + by + threadIdx.x] = round_tf32(t[threadIdx.x][i]);
}

// bc[n] = bl[n] + sum_k bv[k] * WleT[n][k]  -- one block per n, tree reduction
__global__ void bc_kernel(const float* __restrict__ bl, const float* __restrict__ bv,
                          const float* __restrict__ WleT, float* __restrict__ bc) {
    const int n = blockIdx.x, t = threadIdx.x;
    __shared__ float red[256];
    float s = 0.f;
    for (int k = t; k < DM; k += 256) s += bv[k] * WleT[n * DM + k];
    red[t] = s;
    __syncthreads();
#pragma unroll
    for (int o = 128; o >= 32; o >>= 1) {
        if (t < o) red[t] += red[t + o];
        __syncthreads();
    }
    if (t < 32) {
        float v = red[t];
#pragma unroll
        for (int o = 16; o > 0; o >>= 1)
            v += __shfl_down_sync(0xffffffffu, v, o);
        if (t == 0) bc[n] = bl[n] + v;
    }
}

// sum 4 split-K partials -> rounded tf32 output
__global__ void reduce4(const float* __restrict__ p, float* __restrict__ o) {
    int i = (blockIdx.x * 256 + threadIdx.x) * 4;
    float4 a = *(const float4*)&p[i];
    float4 b = *(const float4*)&p[DM * DM + i];
    float4 c = *(const float4*)&p[2 * DM * DM + i];
    float4 d = *(const float4*)&p[3 * DM * DM + i];
    float4 r;
    r.x = round_tf32(a.x + b.x + c.x + d.x);
    r.y = round_tf32(a.y + b.y + c.y + d.y);
    r.z = round_tf32(a.z + b.z + c.z + d.z);
    r.w = round_tf32(a.w + b.w + c.w + d.w);
    *(float4*)&o[i] = r;
}

// fused softmax + 8-way head replication; one block per (q, b)
// If out_att != null: write ONLY the 8 replicas (final GEMM reads replica 0 via cvt).
// Else: write rounded probs back to att scratch.
__global__ void softmax_replicate(float* __restrict__ att, float* __restrict__ out_att) {
    const int q = blockIdx.x, b = blockIdx.y, t = threadIdx.x;
    float* row = att + ((long)(b * SQ + q)) * SK;
    float4 v = ((const float4*)row)[t];

    __shared__ float red[256];
    float m = fmaxf(fmaxf(v.x, v.y), fmaxf(v.z, v.w));
    red[t] = m;
    __syncthreads();
#pragma unroll
    for (int s = 128; s > 0; s >>= 1) {
        if (t < s) red[t] = fmaxf(red[t], red[t + s]);
        __syncthreads();
    }
    m = red[0];
    __syncthreads();

    float4 e;
    e.x = expf(v.x - m); e.y = expf(v.y - m);
    e.z = expf(v.z - m); e.w = expf(v.w - m);
    red[t] = e.x + e.y + e.z + e.w;
    __syncthreads();
#pragma unroll
    for (int s = 128; s > 0; s >>= 1) {
        if (t < s) red[t] += red[t + s];
        __syncthreads();
    }
    float inv = 1.0f / red[0];
    e.x *= inv; e.y *= inv; e.z *= inv; e.w *= inv;

    if (out_att) {
#pragma unroll
        for (int h = 0; h < NH; h++)
            ((float4*)(out_att + (((long)(b * NH + h) * SQ) + q) * SK))[t] = e;
    } else {
        float4 er;
        er.x = round_tf32(e.x); er.y = round_tf32(e.y);
        er.z = round_tf32(e.z); er.w = round_tf32(e.w);
        ((float4*)row)[t] = er;
    }
}

// ================================================================================
// launch
// ================================================================================
extern "C" void kernel_launch(void* const* d_in, const int* in_sizes, int n_in,
                              void* d_out, int out_size) {
    const float* Q    = (const float*)d_in[0];
    const float* K    = (const float*)d_in[1];
    const float* V    = (const float*)d_in[2];
    const int*   mask = (const int*)  d_in[3];
    const float* Wq   = (const float*)d_in[4];
    const float* bq   = (const float*)d_in[5];
    const float* Wk   = (const float*)d_in[6];
    const float* bk   = (const float*)d_in[7];
    const float* Wv   = (const float*)d_in[8];
    const float* bv   = (const float*)d_in[9];
    const float* Wl   = (const float*)d_in[10];
    const float* bl   = (const float*)d_in[11];

    float *Ql, *Kl, *VWt, *att, *wleT, *wqT, *wkT, *wcT, *wcP, *bc;
    cudaGetSymbolAddress((void**)&Ql,   g_Ql);
    cudaGetSymbolAddress((void**)&Kl,   g_Kl);
    cudaGetSymbolAddress((void**)&VWt,  g_VWt);
    cudaGetSymbolAddress((void**)&att,  g_att);
    cudaGetSymbolAddress((void**)&wleT, g_WleT);
    cudaGetSymbolAddress((void**)&wqT,  g_WqT);
    cudaGetSymbolAddress((void**)&wkT,  g_WkT);
    cudaGetSymbolAddress((void**)&wcT,  g_WcT);
    cudaGetSymbolAddress((void**)&wcP,  g_WcP);
    cudaGetSymbolAddress((void**)&bc,   g_bc);

    float* Yout = (float*)d_out;
    const long YSIZE = (long)BATCH * SQ * DM;
    const long ASIZE = (long)BATCH * NH * SQ * SK;
    float* out_att = ((long)out_size >= YSIZE + ASIZE) ? (Yout + YSIZE) : nullptr;
    const float inv_scale = 1.0f / sqrtf((float)DM);

    cudaFuncSetAttribute(gemm_mma<0,1,1>, cudaFuncAttributeMaxDynamicSharedMemorySize, GEMM_SMEM);
    cudaFuncSetAttribute(gemm_mma<0,1,0>, cudaFuncAttributeMaxDynamicSharedMemorySize, GEMM_SMEM);
    cudaFuncSetAttribute(gemm_mma<1,0,0>, cudaFuncAttributeMaxDynamicSharedMemorySize, GEMM_SMEM);
    cudaFuncSetAttribute(gemm_mma<2,1,0>, cudaFuncAttributeMaxDynamicSharedMemorySize, GEMM_SMEM);

    // weight prep
    transpose512_2<<<dim3(16, 16, 2), dim3(32, 8)>>>(Wq, wqT, Wk, wkT);
    wl_sumT_tiled<<<dim3(16, 16), dim3(32, 8)>>>(Wl, wleT);
    bc_kernel<<<DM, 256>>>(bl, bv, wleT, bc);

    // WcT = (Wv @ Wle)^T via split-K (4 x K=128 partials) + reduce
    gemm_mma<2,1,0><<<dim3(DM / BN, DM / BM, 4), 256, GEMM_SMEM>>>(
        Wv, wleT, wcP, 128, 128, 128, (long)DM * DM,
        nullptr, nullptr, 0.f, DM, 0, DM, DM);
    reduce4<<<DM * DM / 1024, 256>>>(wcP, wcT);

    // projections (outputs rounded to tf32 for downstream raw consumption)
    gemm_mma<0,1,1><<<dim3(DM / BN, (BATCH * SQ) / BM, 1), 256, GEMM_SMEM>>>(
        Q, wqT, Ql, DM, 0, 0, 0, bq, nullptr, 0.f, 0, 0, DM, DM);
    gemm_mma<0,1,1><<<dim3(DM / BN, (BATCH * SK) / BM, 1), 256, GEMM_SMEM>>>(
        K, wkT, Kl, DM, 0, 0, 0, bk, nullptr, 0.f, 0, 0, DM, DM);

    // VWt = (V @ Wc)^T per batch: transposed store ldT=SK, fold DM*SK
    gemm_mma<2,1,0><<<dim3(DM / BN, (BATCH * SK) / BM, 1), 256, GEMM_SMEM>>>(
        V, wcT, VWt, DM, 0, 0, 0, nullptr, nullptr, 0.f, SK, (long)DM * SK, DM, DM);

    // scores = Ql @ Kl^T * s + mask
    gemm_mma<1,0,0><<<dim3(SK / BN, SQ / BM, BATCH), 256, GEMM_SMEM>>>(
        Ql, Kl, att, DM, (long)SQ * DM, (long)SK * DM, (long)SQ * SK,
        nullptr, mask, inv_scale, 0, 0, DM, DM);

    // softmax + replicate into att_ws output region (no scratch writeback)
    softmax_replicate<<<dim3(SQ, BATCH), 256>>>(att, out_att);

    // Y = att @ VW + bc ; read probs from att_ws replica 0 (cvt at load)
    const float* attsrc = out_att ? out_att : att;
    const long  attstr  = out_att ? (long)NH * SQ * SK : (long)SQ * SK;
    gemm_mma<0,1,0><<<dim3(DM / BN, SQ / BM, BATCH), 256, GEMM_SMEM>>>(
        attsrc, VWt, Yout, SK, attstr, (long)DM * SK, (long)SQ * DM,
        bc, nullptr, 0.f, 0, 0, SK, SK);
}

// round 7
// speedup vs baseline: 1.2633x; 1.0376x over previous
#include <cuda_runtime.h>
#include <math.h>
#include <stdint.h>

// Problem constants
#define BATCH 8
#define SQ    1024
#define SK    1024
#define DM    512
#define NH    8

// ---------------- device scratch ----------------------------------------------
__device__ float g_Ql[BATCH * SQ * DM];
__device__ float g_Kl[BATCH * SK * DM];
__device__ float g_VWt[BATCH * DM * SK];     // (V @ Wc)^T per batch: [b][d][sk]
__device__ float g_att[BATCH * SQ * SK];
__device__ float g_WleT[DM * DM];
__device__ float g_WqT[DM * DM];
__device__ float g_WkT[DM * DM];
__device__ float g_WcT[DM * DM];
__device__ float g_WcP[4 * DM * DM];         // split-K partials for WcT
__device__ float g_bc[DM];

// ---------------- PTX helpers (sm_80+ features only; plain sm_103 target) ------
__device__ __forceinline__ uint32_t smem_u32(const void* p) {
    uint32_t a;
    asm("{ .reg .u64 t; cvta.to.shared.u64 t, %1; cvt.u32.u64 %0, t; }" : "=r"(a) : "l"(p));
    return a;
}

#define CP_ASYNC16(dst, src) \
    asm volatile("cp.async.cg.shared.global [%0], [%1], 16;" :: "r"(dst), "l"(src) : "memory")
#define CP_COMMIT() asm volatile("cp.async.commit_group;" ::: "memory")
#define CP_WAIT1()  asm volatile("cp.async.wait_group 1;" ::: "memory")
#define CP_WAIT0()  asm volatile("cp.async.wait_group 0;" ::: "memory")

__device__ __forceinline__ uint32_t f2tf32(float v) {
    uint32_t r;
    asm("cvt.rna.tf32.f32 %0, %1;" : "=r"(r) : "f"(v));
    return r;
}
__device__ __forceinline__ float round_tf32(float v) {
    return __uint_as_float(f2tf32(v));
}

__device__ __forceinline__ void mma_tf32(float* c, const uint32_t* a, const uint32_t* b) {
    asm volatile(
        "mma.sync.aligned.m16n8k8.row.col.f32.tf32.tf32.f32 "
        "{%0,%1,%2,%3}, {%4,%5,%6,%7}, {%8,%9}, {%0,%1,%2,%3};"
        : "+f"(c[0]), "+f"(c[1]), "+f"(c[2]), "+f"(c[3])
        : "r"(a[0]), "r"(a[1]), "r"(a[2]), "r"(a[3]), "r"(b[0]), "r"(b[1]));
}

// ================================================================================
// tf32 mma.sync GEMM: C[M,N] = A[M,K(chunk)] @ B[N,K(chunk)]^T
// MODE 0: C += bias[n] (if bias); store rounded to tf32 if ROUND_OUT
// MODE 1: C = C*scale + mask[bz][n]*-1e9
// MODE 2: transposed store (rounded): base C + bz*sC; out[b2*foldT + n*ldT + mloc]
// CVT_A: round A fragments at load; B always consumed raw (pre-rounded producers)
// grid (N/128, M/128, batches-or-ksplits), 256 threads
// ================================================================================
#define BM 128
#define BN 128
#define BK 32
#define LDT 36
#define TILE_F (BM * LDT)
#define GEMM_SMEM (4 * TILE_F * 4)               // 73728 B

template <int MODE, int CVT_A, int ROUND_OUT>
__global__ void __launch_bounds__(256, 2) gemm_mma(
    const float* __restrict__ A, const float* __restrict__ B, float* __restrict__ C,
    int Kdim, long sA, long sB, long sC,
    const float* __restrict__ bias, const int* __restrict__ mask, float scale,
    int ldT, long foldT, int lda, int ldb)
{
    extern __shared__ float smem[];
    float* As[2] = { smem,              smem + TILE_F };
    float* Bs[2] = { smem + 2 * TILE_F, smem + 3 * TILE_F };
    const uint32_t smb = smem_u32(smem);

    const int tid = threadIdx.x;
    const int lane = tid & 31, wid = tid >> 5;
    const int wm = wid >> 2, wn = wid & 3;       // 2 x 4 warps, warp tile 64x32
    const int m0 = blockIdx.y * BM, n0 = blockIdx.x * BN, bz = blockIdx.z;

    const float* Ag = A + (long)bz * sA;
    const float* Bg = B + (long)bz * sB;

    const int lrow[4] = { (tid + 0)   >> 3, (tid + 256) >> 3,
                          (tid + 512) >> 3, (tid + 768) >> 3 };
    const int lcol = (tid & 7) * 4;

    float acc[4][4][4];
#pragma unroll
    for (int i = 0; i < 4; i++)
#pragma unroll
        for (int j = 0; j < 4; j++)
#pragma unroll
            for (int r = 0; r < 4; r++) acc[i][j][r] = 0.f;

    const int NC = Kdim / BK;

    auto issue = [&](int c, int buf) {
        const long k0 = (long)c * BK;
#pragma unroll
        for (int i = 0; i < 4; i++) {
            uint32_t da = smb + (uint32_t)((buf * TILE_F + lrow[i] * LDT + lcol) * 4);
            CP_ASYNC16(da, Ag + (long)(m0 + lrow[i]) * lda + k0 + lcol);
        }
#pragma unroll
        for (int i = 0; i < 4; i++) {
            uint32_t db = smb + (uint32_t)(((2 + buf) * TILE_F + lrow[i] * LDT + lcol) * 4);
            CP_ASYNC16(db, Bg + (long)(n0 + lrow[i]) * ldb + k0 + lcol);
        }
        CP_COMMIT();
    };

    issue(0, 0);

    for (int c = 0; c < NC; c++) {
        const int buf = c & 1;
        if (c + 1 < NC) { issue(c + 1, buf ^ 1); CP_WAIT1(); }
        else            { CP_WAIT0(); }
        __syncthreads();

        const float* Asb = As[buf];
        const float* Bsb = Bs[buf];
        const int ra = wm * 64 + (lane >> 2);
        const int rb = wn * 32 + (lane >> 2);

#pragma unroll
        for (int kk = 0; kk < 4; kk++) {
            const int kb = kk * 8 + (lane & 3);
            uint32_t af[4][4], bf[4][2];
#pragma unroll
            for (int mt = 0; mt < 4; mt++) {
                const float* p = Asb + (ra + mt * 16) * LDT + kb;
                if (CVT_A) {
                    af[mt][0] = f2tf32(p[0]);
                    af[mt][1] = f2tf32(p[8 * LDT]);
                    af[mt][2] = f2tf32(p[4]);
                    af[mt][3] = f2tf32(p[8 * LDT + 4]);
                } else {
                    af[mt][0] = __float_as_uint(p[0]);
                    af[mt][1] = __float_as_uint(p[8 * LDT]);
                    af[mt][2] = __float_as_uint(p[4]);
                    af[mt][3] = __float_as_uint(p[8 * LDT + 4]);
                }
            }
#pragma unroll
            for (int nt = 0; nt < 4; nt++) {
                const float* p = Bsb + (rb + nt * 8) * LDT + kb;
                bf[nt][0] = __float_as_uint(p[0]);
                bf[nt][1] = __float_as_uint(p[4]);
            }
#pragma unroll
            for (int mt = 0; mt < 4; mt++)
#pragma unroll
                for (int nt = 0; nt < 4; nt++)
                    mma_tf32(acc[mt][nt], af[mt], bf[nt]);
        }
        __syncthreads();
    }

    // ---- epilogue ----
    if (MODE == 2) {
        float* Cz = C + (long)bz * sC;
        float* stage = smem;                     // [128][132] (n_local x m_local)
        __syncthreads();
#pragma unroll
        for (int mt = 0; mt < 4; mt++) {
            const int r0 = wm * 64 + mt * 16 + (lane >> 2);
#pragma unroll
            for (int nt = 0; nt < 4; nt++) {
                const int c0 = wn * 32 + nt * 8 + (lane & 3) * 2;
                stage[(c0    ) * 132 + r0    ] = acc[mt][nt][0];
                stage[(c0 + 1) * 132 + r0    ] = acc[mt][nt][1];
                stage[(c0    ) * 132 + r0 + 8] = acc[mt][nt][2];
                stage[(c0 + 1) * 132 + r0 + 8] = acc[mt][nt][3];
            }
        }
        __syncthreads();
        const int b2 = m0 >> 10, mloc = (m0 & 1023) + (tid & 31) * 4;
        const int rq = tid >> 5;
#pragma unroll
        for (int it = 0; it < 16; it++) {
            const int nr = rq + it * 8;
            float4 v = *(const float4*)&stage[nr * 132 + (tid & 31) * 4];
            const float bb = bias ? bias[n0 + nr] : 0.f;
            v.x = round_tf32(v.x + bb); v.y = round_tf32(v.y + bb);
            v.z = round_tf32(v.z + bb); v.w = round_tf32(v.w + bb);
            *(float4*)&Cz[(long)b2 * foldT + (long)(n0 + nr) * ldT + mloc] = v;
        }
        return;
    }

    float* Cg = C + (long)bz * sC;
#pragma unroll
    for (int mt = 0; mt < 4; mt++) {
        const int r0 = m0 + wm * 64 + mt * 16 + (lane >> 2);
#pragma unroll
        for (int nt = 0; nt < 4; nt++) {
            const int c0 = n0 + wn * 32 + nt * 8 + (lane & 3) * 2;
            float2 v0 = { acc[mt][nt][0], acc[mt][nt][1] };
            float2 v1 = { acc[mt][nt][2], acc[mt][nt][3] };
            if (MODE == 0) {
                if (bias) {
                    v0.x += bias[c0]; v0.y += bias[c0 + 1];
                    v1.x += bias[c0]; v1.y += bias[c0 + 1];
                }
                if (ROUND_OUT) {
                    v0.x = round_tf32(v0.x); v0.y = round_tf32(v0.y);
                    v1.x = round_tf32(v1.x); v1.y = round_tf32(v1.y);
                }
            } else { // MODE 1
                const int* mk = mask + (long)bz * SK;
                float p0 = mk[c0] ? -1e9f : 0.f, p1 = mk[c0 + 1] ? -1e9f : 0.f;
                v0.x = v0.x * scale + p0; v0.y = v0.y * scale + p1;
                v1.x = v1.x * scale + p0; v1.y = v1.y * scale + p1;
            }
            *(float2*)&Cg[(long)r0 * gridDim.x * BN + c0]       = v0;
            *(float2*)&Cg[(long)(r0 + 8) * gridDim.x * BN + c0] = v1;
        }
    }
}

// ================================================================================
// helper kernels
// ================================================================================
__global__ void transpose512_2(const float* __restrict__ w0, float* __restrict__ o0,
                               const float* __restrict__ w1, float* __restrict__ o1) {
    __shared__ float t[32][33];
    const float* in  = blockIdx.z ? w1 : w0;
    float*       out = blockIdx.z ? o1 : o0;
    int bx = blockIdx.x * 32, by = blockIdx.y * 32;
    for (int i = threadIdx.y; i < 32; i += 8)
        t[i][threadIdx.x] = in[(by + i) * DM + bx + threadIdx.x];
    __syncthreads();
    for (int i = threadIdx.y; i < 32; i += 8)
        out[(bx + i) * DM + by + threadIdx.x] = round_tf32(t[threadIdx.x][i]);
}

__global__ void wl_sumT_tiled(const float* __restrict__ Wl, float* __restrict__ WleT) {
    __shared__ float t[32][33];
    int bx = blockIdx.x * 32, by = blockIdx.y * 32;   // bx: n, by: k
    for (int i = threadIdx.y; i < 32; i += 8) {
        float s = 0.f;
#pragma unroll
        for (int h = 0; h < NH; h++)
            s += Wl[((long)(h * DM) + by + i) * DM + bx + threadIdx.x];
        t[i][threadIdx.x] = s;
    }
    __syncthreads();
    for (int i = threadIdx.y; i < 32; i += 8)
        WleT[(bx + i) * DM + by + threadIdx.x] = round_tf32(t[threadIdx.x][i]);
}

__global__ void bc_kernel(const float* __restrict__ bl, const float* __restrict__ bv,
                          const float* __restrict__ WleT, float* __restrict__ bc) {
    const int n = blockIdx.x, t = threadIdx.x;
    __shared__ float red[256];
    float s = 0.f;
    for (int k = t; k < DM; k += 256) s += bv[k] * WleT[n * DM + k];
    red[t] = s;
    __syncthreads();
#pragma unroll
    for (int o = 128; o >= 32; o >>= 1) {
        if (t < o) red[t] += red[t + o];
        __syncthreads();
    }
    if (t < 32) {
        float v = red[t];
#pragma unroll
        for (int o = 16; o > 0; o >>= 1)
            v += __shfl_down_sync(0xffffffffu, v, o);
        if (t == 0) bc[n] = bl[n] + v;
    }
}

__global__ void reduce4(const float* __restrict__ p, float* __restrict__ o) {
    int i = (blockIdx.x * 256 + threadIdx.x) * 4;
    float4 a = *(const float4*)&p[i];
    float4 b = *(const float4*)&p[DM * DM + i];
    float4 c = *(const float4*)&p[2 * DM * DM + i];
    float4 d = *(const float4*)&p[3 * DM * DM + i];
    float4 r;
    r.x = round_tf32(a.x + b.x + c.x + d.x);
    r.y = round_tf32(a.y + b.y + c.y + d.y);
    r.z = round_tf32(a.z + b.z + c.z + d.z);
    r.w = round_tf32(a.w + b.w + c.w + d.w);
    *(float4*)&o[i] = r;
}

// fused softmax; writes probs to out_att replica 0 only (or att scratch fallback)
__global__ void softmax_head0(float* __restrict__ att, float* __restrict__ out_att) {
    const int q = blockIdx.x, b = blockIdx.y, t = threadIdx.x;
    float* row = att + ((long)(b * SQ + q)) * SK;
    float4 v = ((const float4*)row)[t];

    __shared__ float red[256];
    float m = fmaxf(fmaxf(v.x, v.y), fmaxf(v.z, v.w));
    red[t] = m;
    __syncthreads();
#pragma unroll
    for (int s = 128; s > 0; s >>= 1) {
        if (t < s) red[t] = fmaxf(red[t], red[t + s]);
        __syncthreads();
    }
    m = red[0];
    __syncthreads();

    float4 e;
    e.x = expf(v.x - m); e.y = expf(v.y - m);
    e.z = expf(v.z - m); e.w = expf(v.w - m);
    red[t] = e.x + e.y + e.z + e.w;
    __syncthreads();
#pragma unroll
    for (int s = 128; s > 0; s >>= 1) {
        if (t < s) red[t] += red[t + s];
        __syncthreads();
    }
    float inv = 1.0f / red[0];
    e.x *= inv; e.y *= inv; e.z *= inv; e.w *= inv;

    if (out_att) {
        ((float4*)(out_att + (((long)(b * NH) * SQ) + q) * SK))[t] = e;
    } else {
        float4 er;
        er.x = round_tf32(e.x); er.y = round_tf32(e.y);
        er.z = round_tf32(e.z); er.w = round_tf32(e.w);
        ((float4*)row)[t] = er;
    }
}

// copy replica 0 -> replicas 1..7 (pure HBM fanout; overlaps final GEMM)
__global__ void replicate7(float* __restrict__ out_att) {
    const int q = blockIdx.x, b = blockIdx.y, t = threadIdx.x;
    const float4* src = (const float4*)(out_att + (((long)(b * NH) * SQ) + q) * SK);
    float4 v = src[t];
#pragma unroll
    for (int h = 1; h < NH; h++)
        ((float4*)(out_att + (((long)(b * NH + h) * SQ) + q) * SK))[t] = v;
}

// ================================================================================
// launch — multi-stream fork/join (graph-capturable via event edges)
// ================================================================================
extern "C" void kernel_launch(void* const* d_in, const int* in_sizes, int n_in,
                              void* d_out, int out_size) {
    const float* Q    = (const float*)d_in[0];
    const float* K    = (const float*)d_in[1];
    const float* V    = (const float*)d_in[2];
    const int*   mask = (const int*)  d_in[3];
    const float* Wq   = (const float*)d_in[4];
    const float* bq   = (const float*)d_in[5];
    const float* Wk   = (const float*)d_in[6];
    const float* bk   = (const float*)d_in[7];
    const float* Wv   = (const float*)d_in[8];
    const float* bv   = (const float*)d_in[9];
    const float* Wl   = (const float*)d_in[10];
    const float* bl   = (const float*)d_in[11];

    float *Ql, *Kl, *VWt, *att, *wleT, *wqT, *wkT, *wcT, *wcP, *bc;
    cudaGetSymbolAddress((void**)&Ql,   g_Ql);
    cudaGetSymbolAddress((void**)&Kl,   g_Kl);
    cudaGetSymbolAddress((void**)&VWt,  g_VWt);
    cudaGetSymbolAddress((void**)&att,  g_att);
    cudaGetSymbolAddress((void**)&wleT, g_WleT);
    cudaGetSymbolAddress((void**)&wqT,  g_WqT);
    cudaGetSymbolAddress((void**)&wkT,  g_WkT);
    cudaGetSymbolAddress((void**)&wcT,  g_WcT);
    cudaGetSymbolAddress((void**)&wcP,  g_WcP);
    cudaGetSymbolAddress((void**)&bc,   g_bc);

    float* Yout = (float*)d_out;
    const long YSIZE = (long)BATCH * SQ * DM;
    const long ASIZE = (long)BATCH * NH * SQ * SK;
    float* out_att = ((long)out_size >= YSIZE + ASIZE) ? (Yout + YSIZE) : nullptr;
    const float inv_scale = 1.0f / sqrtf((float)DM);

    cudaFuncSetAttribute(gemm_mma<0,1,1>, cudaFuncAttributeMaxDynamicSharedMemorySize, GEMM_SMEM);
    cudaFuncSetAttribute(gemm_mma<0,1,0>, cudaFuncAttributeMaxDynamicSharedMemorySize, GEMM_SMEM);
    cudaFuncSetAttribute(gemm_mma<1,0,0>, cudaFuncAttributeMaxDynamicSharedMemorySize, GEMM_SMEM);
    cudaFuncSetAttribute(gemm_mma<2,1,0>, cudaFuncAttributeMaxDynamicSharedMemorySize, GEMM_SMEM);

    // lazily-created side streams + events (capture-safe; no device allocs)
    static cudaStream_t sA = nullptr, sB = nullptr;
    static cudaEvent_t  e0 = nullptr, eA = nullptr, eS = nullptr, eB = nullptr;
    if (!sA) {
        cudaStreamCreateWithFlags(&sA, cudaStreamNonBlocking);
        cudaStreamCreateWithFlags(&sB, cudaStreamNonBlocking);
        cudaEventCreateWithFlags(&e0, cudaEventDisableTiming);
        cudaEventCreateWithFlags(&eA, cudaEventDisableTiming);
        cudaEventCreateWithFlags(&eS, cudaEventDisableTiming);
        cudaEventCreateWithFlags(&eB, cudaEventDisableTiming);
    }
    const bool streams_ok = (sA && sB && e0 && eA && eS && eB);
    cudaStream_t wA = streams_ok ? sA : (cudaStream_t)0;   // weight-prep leg
    cudaStream_t wB = streams_ok ? sB : (cudaStream_t)0;   // replicate leg

    // ---- fork weight-prep leg ----
    if (streams_ok) {
        cudaEventRecord(e0, 0);
        cudaStreamWaitEvent(wA, e0, 0);
    }
    wl_sumT_tiled<<<dim3(16, 16), dim3(32, 8), 0, wA>>>(Wl, wleT);
    bc_kernel<<<DM, 256, 0, wA>>>(bl, bv, wleT, bc);
    gemm_mma<2,1,0><<<dim3(DM / BN, DM / BM, 4), 256, GEMM_SMEM, wA>>>(
        Wv, wleT, wcP, 128, 128, 128, (long)DM * DM,
        nullptr, nullptr, 0.f, DM, 0, DM, DM);
    reduce4<<<DM * DM / 1024, 256, 0, wA>>>(wcP, wcT);
    gemm_mma<2,1,0><<<dim3(DM / BN, (BATCH * SK) / BM, 1), 256, GEMM_SMEM, wA>>>(
        V, wcT, VWt, DM, 0, 0, 0, nullptr, nullptr, 0.f, SK, (long)DM * SK, DM, DM);
    if (streams_ok) cudaEventRecord(eA, wA);

    // ---- main leg: Q/K projections -> scores -> softmax ----
    transpose512_2<<<dim3(16, 16, 2), dim3(32, 8)>>>(Wq, wqT, Wk, wkT);
    gemm_mma<0,1,1><<<dim3(DM / BN, (BATCH * SQ) / BM, 1), 256, GEMM_SMEM>>>(
        Q, wqT, Ql, DM, 0, 0, 0, bq, nullptr, 0.f, 0, 0, DM, DM);
    gemm_mma<0,1,1><<<dim3(DM / BN, (BATCH * SK) / BM, 1), 256, GEMM_SMEM>>>(
        K, wkT, Kl, DM, 0, 0, 0, bk, nullptr, 0.f, 0, 0, DM, DM);
    gemm_mma<1,0,0><<<dim3(SK / BN, SQ / BM, BATCH), 256, GEMM_SMEM>>>(
        Ql, Kl, att, DM, (long)SQ * DM, (long)SK * DM, (long)SQ * SK,
        nullptr, mask, inv_scale, 0, 0, DM, DM);
    softmax_head0<<<dim3(SQ, BATCH), 256>>>(att, out_att);

    // ---- fork replicate leg (only replica 0 needed by final GEMM) ----
    if (out_att) {
        if (streams_ok) {
            cudaEventRecord(eS, 0);
            cudaStreamWaitEvent(wB, eS, 0);
        }
        replicate7<<<dim3(SQ, BATCH), 256, 0, wB>>>(out_att);
        if (streams_ok) cudaEventRecord(eB, wB);
    }

    // ---- join weight-prep; final GEMM ----
    if (streams_ok) cudaStreamWaitEvent(0, eA, 0);
    const float* attsrc = out_att ? out_att : att;
    const long  attstr  = out_att ? (long)NH * SQ * SK : (long)SQ * SK;
    gemm_mma<0,1,0><<<dim3(DM / BN, SQ / BM, BATCH), 256, GEMM_SMEM>>>(
        attsrc, VWt, Yout, SK, attstr, (long)DM * SK, (long)SQ * DM,
        bc, nullptr, 0.f, 0, 0, SK, SK);

    // ---- join replicate leg ----
    if (out_att && streams_ok) cudaStreamWaitEvent(0, eB, 0);
}

// round 8
// speedup vs baseline: 1.4292x; 1.1314x over previous
#include <cuda_runtime.h>
#include <math.h>
#include <stdint.h>

// Problem constants
#define BATCH 8
#define SQ    1024
#define SK    1024
#define DM    512
#define NH    8

// ---------------- device scratch ----------------------------------------------
__device__ float g_Ql[BATCH * SQ * DM];
__device__ float g_Kl[BATCH * SK * DM];
__device__ float g_VWt[BATCH * DM * SK];     // (V @ Wc)^T per batch: [b][d][sk]
__device__ float g_att[BATCH * SQ * SK];
__device__ float g_WleT[DM * DM];
__device__ float g_WqT[DM * DM];
__device__ float g_WkT[DM * DM];
__device__ float g_WcT[DM * DM];
__device__ float g_WcP[4 * DM * DM];         // split-K partials for WcT
__device__ float g_bc[DM];

// ---------------- PTX helpers --------------------------------------------------
__device__ __forceinline__ uint32_t smem_u32(const void* p) {
    uint32_t a;
    asm("{ .reg .u64 t; cvta.to.shared.u64 t, %1; cvt.u32.u64 %0, t; }" : "=r"(a) : "l"(p));
    return a;
}

#define CP_ASYNC16(dst, src) \
    asm volatile("cp.async.cg.shared.global [%0], [%1], 16;" :: "r"(dst), "l"(src) : "memory")
#define CP_COMMIT() asm volatile("cp.async.commit_group;" ::: "memory")
#define CP_WAIT2()  asm volatile("cp.async.wait_group 2;" ::: "memory")
#define CP_WAIT1()  asm volatile("cp.async.wait_group 1;" ::: "memory")
#define CP_WAIT0()  asm volatile("cp.async.wait_group 0;" ::: "memory")

__device__ __forceinline__ uint32_t f2tf32(float v) {
    uint32_t r;
    asm("cvt.rna.tf32.f32 %0, %1;" : "=r"(r) : "f"(v));
    return r;
}
__device__ __forceinline__ float round_tf32(float v) {
    return __uint_as_float(f2tf32(v));
}

__device__ __forceinline__ void mma_tf32(float* c, const uint32_t* a, const uint32_t* b) {
    asm volatile(
        "mma.sync.aligned.m16n8k8.row.col.f32.tf32.tf32.f32 "
        "{%0,%1,%2,%3}, {%4,%5,%6,%7}, {%8,%9}, {%0,%1,%2,%3};"
        : "+f"(c[0]), "+f"(c[1]), "+f"(c[2]), "+f"(c[3])
        : "r"(a[0]), "r"(a[1]), "r"(a[2]), "r"(a[3]), "r"(b[0]), "r"(b[1]));
}

// ================================================================================
// tf32 mma.sync GEMM: C[M,N] = A[M,K] @ B[N,K]^T
// Block tile 256x128x32, 8 warps (4x2), warp tile 64x64, 3-stage cp.async ring
// MODE 0: C += bias[n] (if bias); store rounded to tf32 if ROUND_OUT
// MODE 1: C = C*scale + mask[bz][n]*-1e9
// MODE 2: transposed store (rounded): base C + bz*sC; out[b2*foldT + n*ldT + mloc]
// CVT_A: round A fragments at load; B always consumed raw (pre-rounded producers)
// grid (N/128, M/256, batches-or-ksplits), 256 threads
// ================================================================================
#define BM 256
#define BN 128
#define BK 32
#define LDT 36
#define A_TILE_F (BM * LDT)                      // 9216
#define B_TILE_F (BN * LDT)                      // 4608
#define STAGE_F  (A_TILE_F + B_TILE_F)           // 13824
#define NSTAGE 3
#define GEMM_SMEM (NSTAGE * STAGE_F * 4)         // 165888 B

template <int MODE, int CVT_A, int ROUND_OUT>
__global__ void __launch_bounds__(256, 1) gemm_mma(
    const float* __restrict__ A, const float* __restrict__ B, float* __restrict__ C,
    int Kdim, long sA, long sB, long sC,
    const float* __restrict__ bias, const int* __restrict__ mask, float scale,
    int ldT, long foldT, int lda, int ldb)
{
    extern __shared__ float smem[];
    const uint32_t smb = smem_u32(smem);

    const int tid = threadIdx.x;
    const int lane = tid & 31, wid = tid >> 5;
    const int g = lane >> 2, t = lane & 3;
    const int wm = wid >> 1, wn = wid & 1;       // 4 x 2 warps, warp tile 64x64
    const int m0 = blockIdx.y * BM, n0 = blockIdx.x * BN, bz = blockIdx.z;

    const float* Ag = A + (long)bz * sA;
    const float* Bg = B + (long)bz * sB;

    const int lcol = (tid & 7) * 4;

    float acc[4][8][4];
#pragma unroll
    for (int i = 0; i < 4; i++)
#pragma unroll
        for (int j = 0; j < 8; j++)
#pragma unroll
            for (int r = 0; r < 4; r++) acc[i][j][r] = 0.f;

    const int NC = Kdim / BK;

    auto issue = [&](int c, int s) {
        const long k0 = (long)c * BK;
        const uint32_t abase = smb + (uint32_t)(s * STAGE_F * 4);
        const uint32_t bbase = abase + (uint32_t)(A_TILE_F * 4);
#pragma unroll
        for (int j = 0; j < 8; j++) {
            int row = (tid + 256 * j) >> 3;
            CP_ASYNC16(abase + (uint32_t)((row * LDT + lcol) * 4),
                       Ag + (long)(m0 + row) * lda + k0 + lcol);
        }
#pragma unroll
        for (int j = 0; j < 4; j++) {
            int row = (tid + 256 * j) >> 3;
            CP_ASYNC16(bbase + (uint32_t)((row * LDT + lcol) * 4),
                       Bg + (long)(n0 + row) * ldb + k0 + lcol);
        }
        CP_COMMIT();
    };

    issue(0, 0);
    if (NC > 1) issue(1, 1);

    for (int c = 0; c < NC; c++) {
        const int buf = c % NSTAGE;
        if (c + 2 < NC) { issue(c + 2, (c + 2) % NSTAGE); CP_WAIT2(); }
        else if (c + 1 < NC) { CP_WAIT1(); }
        else { CP_WAIT0(); }
        __syncthreads();

        const float* Asb = smem + buf * STAGE_F;
        const float* Bsb = Asb + A_TILE_F;
        const int ra = wm * 64 + g;
        const int rb = wn * 64 + g;

#pragma unroll
        for (int kk = 0; kk < 4; kk++) {
            const int kb = kk * 8 + t;
            uint32_t af[4][4], bf[8][2];
#pragma unroll
            for (int mt = 0; mt < 4; mt++) {
                const float* p = Asb + (ra + mt * 16) * LDT + kb;
                if (CVT_A) {
                    af[mt][0] = f2tf32(p[0]);
                    af[mt][1] = f2tf32(p[8 * LDT]);
                    af[mt][2] = f2tf32(p[4]);
                    af[mt][3] = f2tf32(p[8 * LDT + 4]);
                } else {
                    af[mt][0] = __float_as_uint(p[0]);
                    af[mt][1] = __float_as_uint(p[8 * LDT]);
                    af[mt][2] = __float_as_uint(p[4]);
                    af[mt][3] = __float_as_uint(p[8 * LDT + 4]);
                }
            }
#pragma unroll
            for (int nt = 0; nt < 8; nt++) {
                const float* p = Bsb + (rb + nt * 8) * LDT + kb;
                bf[nt][0] = __float_as_uint(p[0]);
                bf[nt][1] = __float_as_uint(p[4]);
            }
#pragma unroll
            for (int mt = 0; mt < 4; mt++)
#pragma unroll
                for (int nt = 0; nt < 8; nt++)
                    mma_tf32(acc[mt][nt], af[mt], bf[nt]);
        }
        __syncthreads();
    }

    // ---- epilogue ----
    if (MODE == 2) {
        float* Cz = C + (long)bz * sC;
        float* stage = smem;                     // [128][260] (n_local x m_local)
#pragma unroll
        for (int mt = 0; mt < 4; mt++) {
            const int r0 = wm * 64 + mt * 16 + g;
#pragma unroll
            for (int nt = 0; nt < 8; nt++) {
                const int c0 = wn * 64 + nt * 8 + t * 2;
                stage[(c0    ) * 260 + r0    ] = acc[mt][nt][0];
                stage[(c0 + 1) * 260 + r0    ] = acc[mt][nt][1];
                stage[(c0    ) * 260 + r0 + 8] = acc[mt][nt][2];
                stage[(c0 + 1) * 260 + r0 + 8] = acc[mt][nt][3];
            }
        }
        __syncthreads();
        const int b2 = m0 >> 10, mq = tid & 63, rq = tid >> 6;
        const int mloc = (m0 & 1023) + mq * 4;
#pragma unroll
        for (int it = 0; it < 32; it++) {
            const int nr = rq + it * 4;
            float4 v = *(const float4*)&stage[nr * 260 + mq * 4];
            const float bb = bias ? bias[n0 + nr] : 0.f;
            v.x = round_tf32(v.x + bb); v.y = round_tf32(v.y + bb);
            v.z = round_tf32(v.z + bb); v.w = round_tf32(v.w + bb);
            *(float4*)&Cz[(long)b2 * foldT + (long)(n0 + nr) * ldT + mloc] = v;
        }
        return;
    }

    float* Cg = C + (long)bz * sC;
    const int ldc = gridDim.x * BN;
#pragma unroll
    for (int mt = 0; mt < 4; mt++) {
        const int r0 = m0 + wm * 64 + mt * 16 + g;
#pragma unroll
        for (int nt = 0; nt < 8; nt++) {
            const int c0 = n0 + wn * 64 + nt * 8 + t * 2;
            float2 v0 = { acc[mt][nt][0], acc[mt][nt][1] };
            float2 v1 = { acc[mt][nt][2], acc[mt][nt][3] };
            if (MODE == 0) {
                if (bias) {
                    v0.x += bias[c0]; v0.y += bias[c0 + 1];
                    v1.x += bias[c0]; v1.y += bias[c0 + 1];
                }
                if (ROUND_OUT) {
                    v0.x = round_tf32(v0.x); v0.y = round_tf32(v0.y);
                    v1.x = round_tf32(v1.x); v1.y = round_tf32(v1.y);
                }
            } else { // MODE 1
                const int* mk = mask + (long)bz * SK;
                float p0 = mk[c0] ? -1e9f : 0.f, p1 = mk[c0 + 1] ? -1e9f : 0.f;
                v0.x = v0.x * scale + p0; v0.y = v0.y * scale + p1;
                v1.x = v1.x * scale + p0; v1.y = v1.y * scale + p1;
            }
            *(float2*)&Cg[(long)r0 * ldc + c0]       = v0;
            *(float2*)&Cg[(long)(r0 + 8) * ldc + c0] = v1;
        }
    }
}

// ================================================================================
// helper kernels
// ================================================================================
__global__ void transpose512_2(const float* __restrict__ w0, float* __restrict__ o0,
                               const float* __restrict__ w1, float* __restrict__ o1) {
    __shared__ float t[32][33];
    const float* in  = blockIdx.z ? w1 : w0;
    float*       out = blockIdx.z ? o1 : o0;
    int bx = blockIdx.x * 32, by = blockIdx.y * 32;
    for (int i = threadIdx.y; i < 32; i += 8)
        t[i][threadIdx.x] = in[(by + i) * DM + bx + threadIdx.x];
    __syncthreads();
    for (int i = threadIdx.y; i < 32; i += 8)
        out[(bx + i) * DM + by + threadIdx.x] = round_tf32(t[threadIdx.x][i]);
}

__global__ void wl_sumT_tiled(const float* __restrict__ Wl, float* __restrict__ WleT) {
    __shared__ float t[32][33];
    int bx = blockIdx.x * 32, by = blockIdx.y * 32;   // bx: n, by: k
    for (int i = threadIdx.y; i < 32; i += 8) {
        float s = 0.f;
#pragma unroll
        for (int h = 0; h < NH; h++)
            s += Wl[((long)(h * DM) + by + i) * DM + bx + threadIdx.x];
        t[i][threadIdx.x] = s;
    }
    __syncthreads();
    for (int i = threadIdx.y; i < 32; i += 8)
        WleT[(bx + i) * DM + by + threadIdx.x] = round_tf32(t[threadIdx.x][i]);
}

__global__ void bc_kernel(const float* __restrict__ bl, const float* __restrict__ bv,
                          const float* __restrict__ WleT, float* __restrict__ bc) {
    const int n = blockIdx.x, t = threadIdx.x;
    __shared__ float red[256];
    float s = 0.f;
    for (int k = t; k < DM; k += 256) s += bv[k] * WleT[n * DM + k];
    red[t] = s;
    __syncthreads();
#pragma unroll
    for (int o = 128; o >= 32; o >>= 1) {
        if (t < o) red[t] += red[t + o];
        __syncthreads();
    }
    if (t < 32) {
        float v = red[t];
#pragma unroll
        for (int o = 16; o > 0; o >>= 1)
            v += __shfl_down_sync(0xffffffffu, v, o);
        if (t == 0) bc[n] = bl[n] + v;
    }
}

__global__ void reduce4(const float* __restrict__ p, float* __restrict__ o) {
    int i = (blockIdx.x * 256 + threadIdx.x) * 4;
    float4 a = *(const float4*)&p[i];
    float4 b = *(const float4*)&p[DM * DM + i];
    float4 c = *(const float4*)&p[2 * DM * DM + i];
    float4 d = *(const float4*)&p[3 * DM * DM + i];
    float4 r;
    r.x = round_tf32(a.x + b.x + c.x + d.x);
    r.y = round_tf32(a.y + b.y + c.y + d.y);
    r.z = round_tf32(a.z + b.z + c.z + d.z);
    r.w = round_tf32(a.w + b.w + c.w + d.w);
    *(float4*)&o[i] = r;
}

// fused softmax; writes probs to out_att replica 0 only (or att scratch fallback)
__global__ void softmax_head0(float* __restrict__ att, float* __restrict__ out_att) {
    const int q = blockIdx.x, b = blockIdx.y, t = threadIdx.x;
    float* row = att + ((long)(b * SQ + q)) * SK;
    float4 v = ((const float4*)row)[t];

    __shared__ float red[256];
    float m = fmaxf(fmaxf(v.x, v.y), fmaxf(v.z, v.w));
    red[t] = m;
    __syncthreads();
#pragma unroll
    for (int s = 128; s > 0; s >>= 1) {
        if (t < s) red[t] = fmaxf(red[t], red[t + s]);
        __syncthreads();
    }
    m = red[0];
    __syncthreads();

    float4 e;
    e.x = expf(v.x - m); e.y = expf(v.y - m);
    e.z = expf(v.z - m); e.w = expf(v.w - m);
    red[t] = e.x + e.y + e.z + e.w;
    __syncthreads();
#pragma unroll
    for (int s = 128; s > 0; s >>= 1) {
        if (t < s) red[t] += red[t + s];
        __syncthreads();
    }
    float inv = 1.0f / red[0];
    e.x *= inv; e.y *= inv; e.z *= inv; e.w *= inv;

    if (out_att) {
        ((float4*)(out_att + (((long)(b * NH) * SQ) + q) * SK))[t] = e;
    } else {
        float4 er;
        er.x = round_tf32(e.x); er.y = round_tf32(e.y);
        er.z = round_tf32(e.z); er.w = round_tf32(e.w);
        ((float4*)row)[t] = er;
    }
}

// copy replica 0 -> replicas 1..7 (pure HBM fanout; overlaps final GEMM)
__global__ void replicate7(float* __restrict__ out_att) {
    const int q = blockIdx.x, b = blockIdx.y, t = threadIdx.x;
    const float4* src = (const float4*)(out_att + (((long)(b * NH) * SQ) + q) * SK);
    float4 v = src[t];
#pragma unroll
    for (int h = 1; h < NH; h++)
        ((float4*)(out_att + (((long)(b * NH + h) * SQ) + q) * SK))[t] = v;
}

// ================================================================================
// launch — multi-stream fork/join (graph-capturable via event edges)
// ================================================================================
extern "C" void kernel_launch(void* const* d_in, const int* in_sizes, int n_in,
                              void* d_out, int out_size) {
    const float* Q    = (const float*)d_in[0];
    const float* K    = (const float*)d_in[1];
    const float* V    = (const float*)d_in[2];
    const int*   mask = (const int*)  d_in[3];
    const float* Wq   = (const float*)d_in[4];
    const float* bq   = (const float*)d_in[5];
    const float* Wk   = (const float*)d_in[6];
    const float* bk   = (const float*)d_in[7];
    const float* Wv   = (const float*)d_in[8];
    const float* bv   = (const float*)d_in[9];
    const float* Wl   = (const float*)d_in[10];
    const float* bl   = (const float*)d_in[11];

    float *Ql, *Kl, *VWt, *att, *wleT, *wqT, *wkT, *wcT, *wcP, *bc;
    cudaGetSymbolAddress((void**)&Ql,   g_Ql);
    cudaGetSymbolAddress((void**)&Kl,   g_Kl);
    cudaGetSymbolAddress((void**)&VWt,  g_VWt);
    cudaGetSymbolAddress((void**)&att,  g_att);
    cudaGetSymbolAddress((void**)&wleT, g_WleT);
    cudaGetSymbolAddress((void**)&wqT,  g_WqT);
    cudaGetSymbolAddress((void**)&wkT,  g_WkT);
    cudaGetSymbolAddress((void**)&wcT,  g_WcT);
    cudaGetSymbolAddress((void**)&wcP,  g_WcP);
    cudaGetSymbolAddress((void**)&bc,   g_bc);

    float* Yout = (float*)d_out;
    const long YSIZE = (long)BATCH * SQ * DM;
    const long ASIZE = (long)BATCH * NH * SQ * SK;
    float* out_att = ((long)out_size >= YSIZE + ASIZE) ? (Yout + YSIZE) : nullptr;
    const float inv_scale = 1.0f / sqrtf((float)DM);

    cudaFuncSetAttribute(gemm_mma<0,1,1>, cudaFuncAttributeMaxDynamicSharedMemorySize, GEMM_SMEM);
    cudaFuncSetAttribute(gemm_mma<0,1,0>, cudaFuncAttributeMaxDynamicSharedMemorySize, GEMM_SMEM);
    cudaFuncSetAttribute(gemm_mma<1,0,0>, cudaFuncAttributeMaxDynamicSharedMemorySize, GEMM_SMEM);
    cudaFuncSetAttribute(gemm_mma<2,1,0>, cudaFuncAttributeMaxDynamicSharedMemorySize, GEMM_SMEM);

    // lazily-created side streams + events (capture-safe; no device allocs)
    static cudaStream_t sA = nullptr, sB = nullptr;
    static cudaEvent_t  e0 = nullptr, eA = nullptr, eS = nullptr, eB = nullptr;
    if (!sA) {
        cudaStreamCreateWithFlags(&sA, cudaStreamNonBlocking);
        cudaStreamCreateWithFlags(&sB, cudaStreamNonBlocking);
        cudaEventCreateWithFlags(&e0, cudaEventDisableTiming);
        cudaEventCreateWithFlags(&eA, cudaEventDisableTiming);
        cudaEventCreateWithFlags(&eS, cudaEventDisableTiming);
        cudaEventCreateWithFlags(&eB, cudaEventDisableTiming);
    }
    const bool streams_ok = (sA && sB && e0 && eA && eS && eB);
    cudaStream_t wA = streams_ok ? sA : (cudaStream_t)0;   // weight-prep leg
    cudaStream_t wB = streams_ok ? sB : (cudaStream_t)0;   // replicate leg

    // ---- fork weight-prep leg ----
    if (streams_ok) {
        cudaEventRecord(e0, 0);
        cudaStreamWaitEvent(wA, e0, 0);
    }
    wl_sumT_tiled<<<dim3(16, 16), dim3(32, 8), 0, wA>>>(Wl, wleT);
    bc_kernel<<<DM, 256, 0, wA>>>(bl, bv, wleT, bc);
    gemm_mma<2,1,0><<<dim3(DM / BN, DM / BM, 4), 256, GEMM_SMEM, wA>>>(
        Wv, wleT, wcP, 128, 128, 128, (long)DM * DM,
        nullptr, nullptr, 0.f, DM, 0, DM, DM);
    reduce4<<<DM * DM / 1024, 256, 0, wA>>>(wcP, wcT);
    gemm_mma<2,1,0><<<dim3(DM / BN, (BATCH * SK) / BM, 1), 256, GEMM_SMEM, wA>>>(
        V, wcT, VWt, DM, 0, 0, 0, nullptr, nullptr, 0.f, SK, (long)DM * SK, DM, DM);
    if (streams_ok) cudaEventRecord(eA, wA);

    // ---- main leg: Q/K projections -> scores -> softmax ----
    transpose512_2<<<dim3(16, 16, 2), dim3(32, 8)>>>(Wq, wqT, Wk, wkT);
    gemm_mma<0,1,1><<<dim3(DM / BN, (BATCH * SQ) / BM, 1), 256, GEMM_SMEM>>>(
        Q, wqT, Ql, DM, 0, 0, 0, bq, nullptr, 0.f, 0, 0, DM, DM);
    gemm_mma<0,1,1><<<dim3(DM / BN, (BATCH * SK) / BM, 1), 256, GEMM_SMEM>>>(
        K, wkT, Kl, DM, 0, 0, 0, bk, nullptr, 0.f, 0, 0, DM, DM);
    gemm_mma<1,0,0><<<dim3(SK / BN, SQ / BM, BATCH), 256, GEMM_SMEM>>>(
        Ql, Kl, att, DM, (long)SQ * DM, (long)SK * DM, (long)SQ * SK,
        nullptr, mask, inv_scale, 0, 0, DM, DM);
    softmax_head0<<<dim3(SQ, BATCH), 256>>>(att, out_att);

    // ---- fork replicate leg (only replica 0 needed by final GEMM) ----
    if (out_att) {
        if (streams_ok) {
            cudaEventRecord(eS, 0);
            cudaStreamWaitEvent(wB, eS, 0);
        }
        replicate7<<<dim3(SQ, BATCH), 256, 0, wB>>>(out_att);
        if (streams_ok) cudaEventRecord(eB, wB);
    }

    // ---- join weight-prep; final GEMM ----
    if (streams_ok) cudaStreamWaitEvent(0, eA, 0);
    const float* attsrc = out_att ? out_att : att;
    const long  attstr  = out_att ? (long)NH * SQ * SK : (long)SQ * SK;
    gemm_mma<0,1,0><<<dim3(DM / BN, SQ / BM, BATCH), 256, GEMM_SMEM>>>(
        attsrc, VWt, Yout, SK, attstr, (long)DM * SK, (long)SQ * DM,
        bc, nullptr, 0.f, 0, 0, SK, SK);

    // ---- join replicate leg ----
    if (out_att && streams_ok) cudaStreamWaitEvent(0, eB, 0);
}

// round 9
// speedup vs baseline: 1.9183x; 1.3422x over previous
#include <cuda_runtime.h>
#include <cuda_fp16.h>
#include <math.h>
#include <stdint.h>

// Problem constants
#define BATCH 8
#define SQ    1024
#define SK    1024
#define DM    512
#define NH    8

// ---------------- device scratch ----------------------------------------------
__device__ __half g_Qh[BATCH * SQ * DM];
__device__ __half g_Kh[BATCH * SK * DM];
__device__ __half g_Vh[BATCH * SK * DM];
__device__ __half g_Wvh[DM * DM];
__device__ __half g_Ql[BATCH * SQ * DM];
__device__ __half g_Kl[BATCH * SK * DM];
__device__ __half g_VWt[BATCH * DM * SK];    // (V @ Wc)^T per batch: [b][d][sk]
__device__ float  g_att[BATCH * SQ * SK];    // fp32 scores
__device__ __half g_att_h[BATCH * SQ * SK];  // fp16 probs (final GEMM A)
__device__ __half g_WleT[DM * DM];
__device__ __half g_WqT[DM * DM];
__device__ __half g_WkT[DM * DM];
__device__ __half g_WcT[DM * DM];
__device__ __half g_WcP[4 * DM * DM];        // split-K partials for WcT
__device__ float  g_bc[DM];

// ---------------- PTX helpers --------------------------------------------------
__device__ __forceinline__ uint32_t smem_u32(const void* p) {
    uint32_t a;
    asm("{ .reg .u64 t; cvta.to.shared.u64 t, %1; cvt.u32.u64 %0, t; }" : "=r"(a) : "l"(p));
    return a;
}

#define CP_ASYNC16(dst, src) \
    asm volatile("cp.async.cg.shared.global [%0], [%1], 16;" :: "r"(dst), "l"(src) : "memory")
#define CP_COMMIT() asm volatile("cp.async.commit_group;" ::: "memory")
#define CP_WAIT2()  asm volatile("cp.async.wait_group 2;" ::: "memory")
#define CP_WAIT1()  asm volatile("cp.async.wait_group 1;" ::: "memory")
#define CP_WAIT0()  asm volatile("cp.async.wait_group 0;" ::: "memory")

__device__ __forceinline__ void mma_f16(float* c, const uint32_t* a, const uint32_t* b) {
    asm volatile(
        "mma.sync.aligned.m16n8k16.row.col.f32.f16.f16.f32 "
        "{%0,%1,%2,%3}, {%4,%5,%6,%7}, {%8,%9}, {%0,%1,%2,%3};"
        : "+f"(c[0]), "+f"(c[1]), "+f"(c[2]), "+f"(c[3])
        : "r"(a[0]), "r"(a[1]), "r"(a[2]), "r"(a[3]), "r"(b[0]), "r"(b[1]));
}

// ================================================================================
// fp16 mma.sync GEMM: C[M,N] = A[M,K] @ B[N,K]^T   (A, B fp16, fp32 accumulate)
// Block tile 256x128x32, 8 warps (4x2), warp tile 64x64, 3-stage cp.async ring
// MODE 0: C += bias[n]; output fp16 if OUT_HALF else fp32
// MODE 1: C = C*scale + mask[bz][n]*-1e9 (fp32 out)
// MODE 2: transposed fp16 store: out[b2*foldT + n*ldT + mloc]
// grid (N/128, M/256, batches-or-ksplits), 256 threads
// ================================================================================
#define BM 256
#define BN 128
#define BK 32
#define LDH 40                                   // smem row stride in halves
#define A_TILE_H (BM * LDH)                      // 10240
#define B_TILE_H (BN * LDH)                      // 5120
#define STAGE_H  (A_TILE_H + B_TILE_H)           // 15360
#define NSTAGE 3
#define GEMM_SMEM (NSTAGE * STAGE_H * 2)         // 92160 B

template <int MODE, int OUT_HALF>
__global__ void __launch_bounds__(256, 1) gemm_h(
    const __half* __restrict__ A, const __half* __restrict__ B, void* __restrict__ Cv,
    int Kdim, long sA, long sB, long sC,
    const float* __restrict__ bias, const int* __restrict__ mask, float scale,
    int ldT, long foldT, int lda, int ldb)
{
    extern __shared__ __half smem[];
    const uint32_t smb = smem_u32(smem);

    const int tid = threadIdx.x;
    const int lane = tid & 31, wid = tid >> 5;
    const int g = lane >> 2, t = lane & 3;
    const int wm = wid >> 1, wn = wid & 1;       // 4 x 2 warps, warp tile 64x64
    const int m0 = blockIdx.y * BM, n0 = blockIdx.x * BN, bz = blockIdx.z;

    const __half* Ag = A + (long)bz * sA;
    const __half* Bg = B + (long)bz * sB;

    float acc[4][8][4];
#pragma unroll
    for (int i = 0; i < 4; i++)
#pragma unroll
        for (int j = 0; j < 8; j++)
#pragma unroll
            for (int r = 0; r < 4; r++) acc[i][j][r] = 0.f;

    const int NC = Kdim / BK;
    const int lrow = tid >> 2, lchunk = (tid & 3) * 8;   // 8 halves = 16B per chunk

    auto issue = [&](int c, int s) {
        const long k0 = (long)c * BK;
        const uint32_t abase = smb + (uint32_t)(s * STAGE_H * 2);
        const uint32_t bbase = abase + (uint32_t)(A_TILE_H * 2);
#pragma unroll
        for (int j = 0; j < 4; j++) {
            int row = lrow + 64 * j;
            CP_ASYNC16(abase + (uint32_t)((row * LDH + lchunk) * 2),
                       Ag + (long)(m0 + row) * lda + k0 + lchunk);
        }
#pragma unroll
        for (int j = 0; j < 2; j++) {
            int row = lrow + 64 * j;
            CP_ASYNC16(bbase + (uint32_t)((row * LDH + lchunk) * 2),
                       Bg + (long)(n0 + row) * ldb + k0 + lchunk);
        }
        CP_COMMIT();
    };

    issue(0, 0);
    if (NC > 1) issue(1, 1);

    for (int c = 0; c < NC; c++) {
        const int buf = c % NSTAGE;
        if (c + 2 < NC) { issue(c + 2, (c + 2) % NSTAGE); CP_WAIT2(); }
        else if (c + 1 < NC) { CP_WAIT1(); }
        else { CP_WAIT0(); }
        __syncthreads();

        const __half* Asb = smem + buf * STAGE_H;
        const __half* Bsb = Asb + A_TILE_H;
        const int ra = wm * 64 + g;
        const int rb = wn * 64 + g;

#pragma unroll
        for (int kk = 0; kk < 2; kk++) {             // two k16 steps per BK=32
            const int kb = kk * 16 + 2 * t;
            uint32_t af[4][4], bf[8][2];
#pragma unroll
            for (int mt = 0; mt < 4; mt++) {
                const __half* p0 = Asb + (ra + mt * 16) * LDH + kb;
                const __half* p1 = Asb + (ra + mt * 16 + 8) * LDH + kb;
                af[mt][0] = *(const uint32_t*)(p0);
                af[mt][1] = *(const uint32_t*)(p1);
                af[mt][2] = *(const uint32_t*)(p0 + 8);
                af[mt][3] = *(const uint32_t*)(p1 + 8);
            }
#pragma unroll
            for (int nt = 0; nt < 8; nt++) {
                const __half* p = Bsb + (rb + nt * 8) * LDH + kb;
                bf[nt][0] = *(const uint32_t*)(p);
                bf[nt][1] = *(const uint32_t*)(p + 8);
            }
#pragma unroll
            for (int mt = 0; mt < 4; mt++)
#pragma unroll
                for (int nt = 0; nt < 8; nt++)
                    mma_f16(acc[mt][nt], af[mt], bf[nt]);
        }
        __syncthreads();
    }

    // ---- epilogue ----
    if (MODE == 2) {
        __half* Cz = (__half*)Cv + (long)bz * sC;
        __half* stage = smem;                    // [128][264] halves (n x m)
#pragma unroll
        for (int mt = 0; mt < 4; mt++) {
            const int r0 = wm * 64 + mt * 16 + g;
#pragma unroll
            for (int nt = 0; nt < 8; nt++) {
                const int c0 = wn * 64 + nt * 8 + t * 2;
                stage[(c0    ) * 264 + r0    ] = __float2half_rn(acc[mt][nt][0]);
                stage[(c0 + 1) * 264 + r0    ] = __float2half_rn(acc[mt][nt][1]);
                stage[(c0    ) * 264 + r0 + 8] = __float2half_rn(acc[mt][nt][2]);
                stage[(c0 + 1) * 264 + r0 + 8] = __float2half_rn(acc[mt][nt][3]);
            }
        }
        __syncthreads();
        const int b2 = m0 >> 10, mq = tid & 63, rq = tid >> 6;
        const int mloc = (m0 & 1023) + mq * 4;
#pragma unroll
        for (int it = 0; it < 32; it++) {
            const int nr = rq + it * 4;
            uint2 v = *(const uint2*)&stage[nr * 264 + mq * 4];
            *(uint2*)&Cz[(long)b2 * foldT + (long)(n0 + nr) * ldT + mloc] = v;
        }
        return;
    }

    const int ldc = gridDim.x * BN;
#pragma unroll
    for (int mt = 0; mt < 4; mt++) {
        const int r0 = m0 + wm * 64 + mt * 16 + g;
#pragma unroll
        for (int nt = 0; nt < 8; nt++) {
            const int c0 = n0 + wn * 64 + nt * 8 + t * 2;
            float2 v0 = { acc[mt][nt][0], acc[mt][nt][1] };
            float2 v1 = { acc[mt][nt][2], acc[mt][nt][3] };
            if (MODE == 0) {
                if (bias) {
                    v0.x += bias[c0]; v0.y += bias[c0 + 1];
                    v1.x += bias[c0]; v1.y += bias[c0 + 1];
                }
                if (OUT_HALF) {
                    __half* Cg = (__half*)Cv + (long)bz * sC;
                    *(__half2*)&Cg[(long)r0 * ldc + c0]       = __floats2half2_rn(v0.x, v0.y);
                    *(__half2*)&Cg[(long)(r0 + 8) * ldc + c0] = __floats2half2_rn(v1.x, v1.y);
                    continue;
                }
            } else { // MODE 1
                const int* mk = mask + (long)bz * SK;
                float p0 = mk[c0] ? -1e9f : 0.f, p1 = mk[c0 + 1] ? -1e9f : 0.f;
                v0.x = v0.x * scale + p0; v0.y = v0.y * scale + p1;
                v1.x = v1.x * scale + p0; v1.y = v1.y * scale + p1;
            }
            float* Cg = (float*)Cv + (long)bz * sC;
            *(float2*)&Cg[(long)r0 * ldc + c0]       = v0;
            *(float2*)&Cg[(long)(r0 + 8) * ldc + c0] = v1;
        }
    }
}

// ================================================================================
// helper kernels
// ================================================================================
__global__ void f32_to_f16(const float* __restrict__ in, __half* __restrict__ out) {
    long i = ((long)blockIdx.x * 256 + threadIdx.x) * 4;
    float4 v = *(const float4*)&in[i];
    __half2 h0 = __floats2half2_rn(v.x, v.y);
    __half2 h1 = __floats2half2_rn(v.z, v.w);
    uint2 p = { *(uint32_t*)&h0, *(uint32_t*)&h1 };
    *(uint2*)&out[i] = p;
}

__global__ void transpose512_2(const float* __restrict__ w0, __half* __restrict__ o0,
                               const float* __restrict__ w1, __half* __restrict__ o1) {
    __shared__ float t[32][33];
    const float* in  = blockIdx.z ? w1 : w0;
    __half*      out = blockIdx.z ? o1 : o0;
    int bx = blockIdx.x * 32, by = blockIdx.y * 32;
    for (int i = threadIdx.y; i < 32; i += 8)
        t[i][threadIdx.x] = in[(by + i) * DM + bx + threadIdx.x];
    __syncthreads();
    for (int i = threadIdx.y; i < 32; i += 8)
        out[(bx + i) * DM + by + threadIdx.x] = __float2half_rn(t[threadIdx.x][i]);
}

__global__ void wl_sumT_tiled(const float* __restrict__ Wl, __half* __restrict__ WleT) {
    __shared__ float t[32][33];
    int bx = blockIdx.x * 32, by = blockIdx.y * 32;   // bx: n, by: k
    for (int i = threadIdx.y; i < 32; i += 8) {
        float s = 0.f;
#pragma unroll
        for (int h = 0; h < NH; h++)
            s += Wl[((long)(h * DM) + by + i) * DM + bx + threadIdx.x];
        t[i][threadIdx.x] = s;
    }
    __syncthreads();
    for (int i = threadIdx.y; i < 32; i += 8)
        WleT[(bx + i) * DM + by + threadIdx.x] = __float2half_rn(t[threadIdx.x][i]);
}

__global__ void bc_kernel(const float* __restrict__ bl, const float* __restrict__ bv,
                          const __half* __restrict__ WleT, float* __restrict__ bc) {
    const int n = blockIdx.x, t = threadIdx.x;
    __shared__ float red[256];
    float s = 0.f;
    for (int k = t; k < DM; k += 256) s += bv[k] * __half2float(WleT[n * DM + k]);
    red[t] = s;
    __syncthreads();
#pragma unroll
    for (int o = 128; o >= 32; o >>= 1) {
        if (t < o) red[t] += red[t + o];
        __syncthreads();
    }
    if (t < 32) {
        float v = red[t];
#pragma unroll
        for (int o = 16; o > 0; o >>= 1)
            v += __shfl_down_sync(0xffffffffu, v, o);
        if (t == 0) bc[n] = bl[n] + v;
    }
}

// sum 4 fp16 split-K partials -> fp16 output
__global__ void reduce4(const __half* __restrict__ p, __half* __restrict__ o) {
    long i = ((long)blockIdx.x * 256 + threadIdx.x) * 4;
    float s[4];
#pragma unroll
    for (int j = 0; j < 4; j++) s[j] = 0.f;
#pragma unroll
    for (int part = 0; part < 4; part++) {
        uint2 v = *(const uint2*)&p[(long)part * DM * DM + i];
        __half2 h0 = *(__half2*)&v.x, h1 = *(__half2*)&v.y;
        s[0] += __low2float(h0);  s[1] += __high2float(h0);
        s[2] += __low2float(h1);  s[3] += __high2float(h1);
    }
    __half2 r0 = __floats2half2_rn(s[0], s[1]);
    __half2 r1 = __floats2half2_rn(s[2], s[3]);
    uint2 r = { *(uint32_t*)&r0, *(uint32_t*)&r1 };
    *(uint2*)&o[i] = r;
}

// fused softmax; writes fp16 probs to att_h (final GEMM A) + fp32 replica 0
__global__ void softmax_head0(const float* __restrict__ att, __half* __restrict__ att_h,
                              float* __restrict__ out_att) {
    const int q = blockIdx.x, b = blockIdx.y, t = threadIdx.x;
    const float* row = att + ((long)(b * SQ + q)) * SK;
    float4 v = ((const float4*)row)[t];

    __shared__ float red[256];
    float m = fmaxf(fmaxf(v.x, v.y), fmaxf(v.z, v.w));
    red[t] = m;
    __syncthreads();
#pragma unroll
    for (int s = 128; s > 0; s >>= 1) {
        if (t < s) red[t] = fmaxf(red[t], red[t + s]);
        __syncthreads();
    }
    m = red[0];
    __syncthreads();

    float4 e;
    e.x = expf(v.x - m); e.y = expf(v.y - m);
    e.z = expf(v.z - m); e.w = expf(v.w - m);
    red[t] = e.x + e.y + e.z + e.w;
    __syncthreads();
#pragma unroll
    for (int s = 128; s > 0; s >>= 1) {
        if (t < s) red[t] += red[t + s];
        __syncthreads();
    }
    float inv = 1.0f / red[0];
    e.x *= inv; e.y *= inv; e.z *= inv; e.w *= inv;

    __half2 h0 = __floats2half2_rn(e.x, e.y);
    __half2 h1 = __floats2half2_rn(e.z, e.w);
    uint2 ph = { *(uint32_t*)&h0, *(uint32_t*)&h1 };
    ((uint2*)(att_h + ((long)(b * SQ + q)) * SK))[t] = ph;

    if (out_att)
        ((float4*)(out_att + (((long)(b * NH) * SQ) + q) * SK))[t] = e;
}

// copy replica 0 -> replicas 1..7 (pure HBM fanout; overlaps final GEMM)
__global__ void replicate7(float* __restrict__ out_att) {
    const int q = blockIdx.x, b = blockIdx.y, t = threadIdx.x;
    const float4* src = (const float4*)(out_att + (((long)(b * NH) * SQ) + q) * SK);
    float4 v = src[t];
#pragma unroll
    for (int h = 1; h < NH; h++)
        ((float4*)(out_att + (((long)(b * NH + h) * SQ) + q) * SK))[t] = v;
}

// ================================================================================
// launch — multi-stream fork/join (graph-capturable via event edges)
// ================================================================================
extern "C" void kernel_launch(void* const* d_in, const int* in_sizes, int n_in,
                              void* d_out, int out_size) {
    const float* Q    = (const float*)d_in[0];
    const float* K    = (const float*)d_in[1];
    const float* V    = (const float*)d_in[2];
    const int*   mask = (const int*)  d_in[3];
    const float* Wq   = (const float*)d_in[4];
    const float* bq   = (const float*)d_in[5];
    const float* Wk   = (const float*)d_in[6];
    const float* bk   = (const float*)d_in[7];
    const float* Wv   = (const float*)d_in[8];
    const float* bv   = (const float*)d_in[9];
    const float* Wl   = (const float*)d_in[10];
    const float* bl   = (const float*)d_in[11];

    __half *Qh, *Kh, *Vh, *Wvh, *Ql, *Kl, *VWt, *att_h, *wleT, *wqT, *wkT, *wcT, *wcP;
    float *att, *bc;
    cudaGetSymbolAddress((void**)&Qh,    g_Qh);
    cudaGetSymbolAddress((void**)&Kh,    g_Kh);
    cudaGetSymbolAddress((void**)&Vh,    g_Vh);
    cudaGetSymbolAddress((void**)&Wvh,   g_Wvh);
    cudaGetSymbolAddress((void**)&Ql,    g_Ql);
    cudaGetSymbolAddress((void**)&Kl,    g_Kl);
    cudaGetSymbolAddress((void**)&VWt,   g_VWt);
    cudaGetSymbolAddress((void**)&att,   g_att);
    cudaGetSymbolAddress((void**)&att_h, g_att_h);
    cudaGetSymbolAddress((void**)&wleT,  g_WleT);
    cudaGetSymbolAddress((void**)&wqT,   g_WqT);
    cudaGetSymbolAddress((void**)&wkT,   g_WkT);
    cudaGetSymbolAddress((void**)&wcT,   g_WcT);
    cudaGetSymbolAddress((void**)&wcP,   g_WcP);
    cudaGetSymbolAddress((void**)&bc,    g_bc);

    float* Yout = (float*)d_out;
    const long YSIZE = (long)BATCH * SQ * DM;
    const long ASIZE = (long)BATCH * NH * SQ * SK;
    float* out_att = ((long)out_size >= YSIZE + ASIZE) ? (Yout + YSIZE) : nullptr;
    const float inv_scale = 1.0f / sqrtf((float)DM);

    cudaFuncSetAttribute(gemm_h<0,0>, cudaFuncAttributeMaxDynamicSharedMemorySize, GEMM_SMEM);
    cudaFuncSetAttribute(gemm_h<0,1>, cudaFuncAttributeMaxDynamicSharedMemorySize, GEMM_SMEM);
    cudaFuncSetAttribute(gemm_h<1,0>, cudaFuncAttributeMaxDynamicSharedMemorySize, GEMM_SMEM);
    cudaFuncSetAttribute(gemm_h<2,1>, cudaFuncAttributeMaxDynamicSharedMemorySize, GEMM_SMEM);

    // lazily-created side streams + events (capture-safe; no device allocs)
    static cudaStream_t sA = nullptr, sB = nullptr;
    static cudaEvent_t  e0 = nullptr, eA = nullptr, eS = nullptr, eB = nullptr;
    if (!sA) {
        cudaStreamCreateWithFlags(&sA, cudaStreamNonBlocking);
        cudaStreamCreateWithFlags(&sB, cudaStreamNonBlocking);
        cudaEventCreateWithFlags(&e0, cudaEventDisableTiming);
        cudaEventCreateWithFlags(&eA, cudaEventDisableTiming);
        cudaEventCreateWithFlags(&eS, cudaEventDisableTiming);
        cudaEventCreateWithFlags(&eB, cudaEventDisableTiming);
    }
    const bool streams_ok = (sA && sB && e0 && eA && eS && eB);
    cudaStream_t wA = streams_ok ? sA : (cudaStream_t)0;   // weight-prep leg
    cudaStream_t wB = streams_ok ? sB : (cudaStream_t)0;   // replicate leg

    const int NBIG = (BATCH * SQ * DM) / 1024;             // blocks for big converts
    const int NSML = (DM * DM) / 1024;

    // ---- fork weight-prep leg ----
    if (streams_ok) {
        cudaEventRecord(e0, 0);
        cudaStreamWaitEvent(wA, e0, 0);
    }
    f32_to_f16<<<NBIG, 256, 0, wA>>>(V, Vh);
    f32_to_f16<<<NSML, 256, 0, wA>>>(Wv, Wvh);
    wl_sumT_tiled<<<dim3(16, 16), dim3(32, 8), 0, wA>>>(Wl, wleT);
    bc_kernel<<<DM, 256, 0, wA>>>(bl, bv, wleT, bc);
    gemm_h<2,1><<<dim3(DM / BN, DM / BM, 4), 256, GEMM_SMEM, wA>>>(
        Wvh, wleT, wcP, 128, 128, 128, (long)DM * DM,
        nullptr, nullptr, 0.f, DM, 0, DM, DM);
    reduce4<<<DM * DM / 1024, 256, 0, wA>>>(wcP, wcT);
    gemm_h<2,1><<<dim3(DM / BN, (BATCH * SK) / BM, 1), 256, GEMM_SMEM, wA>>>(
        Vh, wcT, VWt, DM, 0, 0, 0, nullptr, nullptr, 0.f, SK, (long)DM * SK, DM, DM);
    if (streams_ok) cudaEventRecord(eA, wA);

    // ---- main leg: convert -> Q/K projections -> scores -> softmax ----
    f32_to_f16<<<NBIG, 256>>>(Q, Qh);
    f32_to_f16<<<NBIG, 256>>>(K, Kh);
    transpose512_2<<<dim3(16, 16, 2), dim3(32, 8)>>>(Wq, wqT, Wk, wkT);
    gemm_h<0,1><<<dim3(DM / BN, (BATCH * SQ) / BM, 1), 256, GEMM_SMEM>>>(
        Qh, wqT, Ql, DM, 0, 0, 0, bq, nullptr, 0.f, 0, 0, DM, DM);
    gemm_h<0,1><<<dim3(DM / BN, (BATCH * SK) / BM, 1), 256, GEMM_SMEM>>>(
        Kh, wkT, Kl, DM, 0, 0, 0, bk, nullptr, 0.f, 0, 0, DM, DM);
    gemm_h<1,0><<<dim3(SK / BN, SQ / BM, BATCH), 256, GEMM_SMEM>>>(
        Ql, Kl, att, DM, (long)SQ * DM, (long)SK * DM, (long)SQ * SK,
        nullptr, mask, inv_scale, 0, 0, DM, DM);
    softmax_head0<<<dim3(SQ, BATCH), 256>>>(att, att_h, out_att);

    // ---- fork replicate leg (final GEMM reads fp16 att_h, not replicas) ----
    if (out_att) {
        if (streams_ok) {
            cudaEventRecord(eS, 0);
            cudaStreamWaitEvent(wB, eS, 0);
        }
        replicate7<<<dim3(SQ, BATCH), 256, 0, wB>>>(out_att);
        if (streams_ok) cudaEventRecord(eB, wB);
    }

    // ---- join weight-prep; final GEMM ----
    if (streams_ok) cudaStreamWaitEvent(0, eA, 0);
    gemm_h<0,0><<<dim3(DM / BN, SQ / BM, BATCH), 256, GEMM_SMEM>>>(
        att_h, VWt, Yout, SK, (long)SQ * SK, (long)DM * SK, (long)SQ * DM,
        bc, nullptr, 0.f, 0, 0, SK, SK);

    // ---- join replicate leg ----
    if (out_att && streams_ok) cudaStreamWaitEvent(0, eB, 0);
}

// round 10
// speedup vs baseline: 1.9339x; 1.0082x over previous
#include <cuda_runtime.h>
#include <cuda_fp16.h>
#include <math.h>
#include <stdint.h>

// Problem constants
#define BATCH 8
#define SQ    1024
#define SK    1024
#define DM    512
#define NH    8

// ---------------- device scratch ----------------------------------------------
__device__ __half g_Qh[BATCH * SQ * DM];
__device__ __half g_Kh[BATCH * SK * DM];
__device__ __half g_Vh[BATCH * SK * DM];
__device__ __half g_Wvh[DM * DM];
__device__ __half g_Ql[BATCH * SQ * DM];
__device__ __half g_Kl[BATCH * SK * DM];
__device__ __half g_VWt[BATCH * DM * SK];    // (V @ Wc)^T per batch: [b][d][sk]
__device__ float  g_att[BATCH * SQ * SK];    // fp32 scores
__device__ __half g_att_h[BATCH * SQ * SK];  // fp16 probs (final GEMM A)
__device__ __half g_WleT[DM * DM];
__device__ __half g_WqT[DM * DM];
__device__ __half g_WkT[DM * DM];
__device__ __half g_WcT[DM * DM];
__device__ __half g_WcP[4 * DM * DM];        // split-K partials for WcT
__device__ float  g_bc[DM];

// ---------------- PTX helpers --------------------------------------------------
__device__ __forceinline__ uint32_t smem_u32(const void* p) {
    uint32_t a;
    asm("{ .reg .u64 t; cvta.to.shared.u64 t, %1; cvt.u32.u64 %0, t; }" : "=r"(a) : "l"(p));
    return a;
}

#define CP_ASYNC16(dst, src) \
    asm volatile("cp.async.cg.shared.global [%0], [%1], 16;" :: "r"(dst), "l"(src) : "memory")
#define CP_COMMIT() asm volatile("cp.async.commit_group;" ::: "memory")
#define CP_WAIT2()  asm volatile("cp.async.wait_group 2;" ::: "memory")
#define CP_WAIT1()  asm volatile("cp.async.wait_group 1;" ::: "memory")
#define CP_WAIT0()  asm volatile("cp.async.wait_group 0;" ::: "memory")

#define LDSM4(r0, r1, r2, r3, addr) \
    asm volatile("ldmatrix.sync.aligned.m8n8.x4.shared.b16 {%0,%1,%2,%3}, [%4];" \
        : "=r"(r0), "=r"(r1), "=r"(r2), "=r"(r3) : "r"(addr))

__device__ __forceinline__ void mma_f16(float* c, const uint32_t* a, const uint32_t* b) {
    asm volatile(
        "mma.sync.aligned.m16n8k16.row.col.f32.f16.f16.f32 "
        "{%0,%1,%2,%3}, {%4,%5,%6,%7}, {%8,%9}, {%0,%1,%2,%3};"
        : "+f"(c[0]), "+f"(c[1]), "+f"(c[2]), "+f"(c[3])
        : "r"(a[0]), "r"(a[1]), "r"(a[2]), "r"(a[3]), "r"(b[0]), "r"(b[1]));
}

// ================================================================================
// fp16 mma.sync GEMM: C[M,N] = A[M,K] @ B[N,K]^T   (A, B fp16, fp32 accumulate)
// Block tile 256x128x32, 8 warps (4x2), warp tile 64x64, 3-stage cp.async ring,
// ldmatrix.x4 fragment loads (conflict-free with LDH=40 stride).
// MODE 0: C += bias[n]; output fp16 if OUT_HALF else fp32
// MODE 1: C = C*scale + mask[bz][n]*-1e9 (fp32 out)
// MODE 2: transposed fp16 store: out[b2*foldT + n*ldT + mloc]
// grid (N/128, M/256, batches-or-ksplits), 256 threads
// ================================================================================
#define BM 256
#define BN 128
#define BK 32
#define LDH 40                                   // smem row stride in halves
#define A_TILE_H (BM * LDH)                      // 10240
#define B_TILE_H (BN * LDH)                      // 5120
#define STAGE_H  (A_TILE_H + B_TILE_H)           // 15360
#define NSTAGE 3
#define GEMM_SMEM (NSTAGE * STAGE_H * 2)         // 92160 B

template <int MODE, int OUT_HALF>
__global__ void __launch_bounds__(256, 1) gemm_h(
    const __half* __restrict__ A, const __half* __restrict__ B, void* __restrict__ Cv,
    int Kdim, long sA, long sB, long sC,
    const float* __restrict__ bias, const int* __restrict__ mask, float scale,
    int ldT, long foldT, int lda, int ldb)
{
    extern __shared__ __half smem[];
    const uint32_t smb = smem_u32(smem);

    const int tid = threadIdx.x;
    const int lane = tid & 31, wid = tid >> 5;
    const int g = lane >> 2, t = lane & 3;
    const int wm = wid >> 1, wn = wid & 1;       // 4 x 2 warps, warp tile 64x64
    const int m0 = blockIdx.y * BM, n0 = blockIdx.x * BN, bz = blockIdx.z;

    const __half* Ag = A + (long)bz * sA;
    const __half* Bg = B + (long)bz * sB;

    float acc[4][8][4];
#pragma unroll
    for (int i = 0; i < 4; i++)
#pragma unroll
        for (int j = 0; j < 8; j++)
#pragma unroll
            for (int r = 0; r < 4; r++) acc[i][j][r] = 0.f;

    const int NC = Kdim / BK;
    const int lrow = tid >> 2, lchunk = (tid & 3) * 8;   // cp.async slots

    // ldmatrix per-lane base offsets (bytes, relative to stage start)
    const int lj = lane >> 3, lr8 = lane & 7;
    uint32_t aoff[4], boff[4];
#pragma unroll
    for (int mt = 0; mt < 4; mt++)
        aoff[mt] = (uint32_t)(((wm * 64 + mt * 16 + lr8 + 8 * (lj & 1)) * LDH
                               + 8 * (lj >> 1)) * 2);
#pragma unroll
    for (int np = 0; np < 4; np++)
        boff[np] = (uint32_t)((A_TILE_H + (wn * 64 + np * 16 + lr8 + 8 * (lj >> 1)) * LDH
                               + 8 * (lj & 1)) * 2);

    auto issue = [&](int c, int s) {
        const long k0 = (long)c * BK;
        const uint32_t abase = smb + (uint32_t)(s * STAGE_H * 2);
        const uint32_t bbase = abase + (uint32_t)(A_TILE_H * 2);
#pragma unroll
        for (int j = 0; j < 4; j++) {
            int row = lrow + 64 * j;
            CP_ASYNC16(abase + (uint32_t)((row * LDH + lchunk) * 2),
                       Ag + (long)(m0 + row) * lda + k0 + lchunk);
        }
#pragma unroll
        for (int j = 0; j < 2; j++) {
            int row = lrow + 64 * j;
            CP_ASYNC16(bbase + (uint32_t)((row * LDH + lchunk) * 2),
                       Bg + (long)(n0 + row) * ldb + k0 + lchunk);
        }
        CP_COMMIT();
    };

    issue(0, 0);
    if (NC > 1) issue(1, 1);

    for (int c = 0; c < NC; c++) {
        const int buf = c % NSTAGE;
        if (c + 2 < NC) { issue(c + 2, (c + 2) % NSTAGE); CP_WAIT2(); }
        else if (c + 1 < NC) { CP_WAIT1(); }
        else { CP_WAIT0(); }
        __syncthreads();

        const uint32_t sbase = smb + (uint32_t)(buf * STAGE_H * 2);

#pragma unroll
        for (int kk = 0; kk < 2; kk++) {             // two k16 steps per BK=32
            const uint32_t kboff = (uint32_t)(kk * 16 * 2);
            uint32_t af[4][4], bf[8][2];
#pragma unroll
            for (int mt = 0; mt < 4; mt++)
                LDSM4(af[mt][0], af[mt][1], af[mt][2], af[mt][3],
                      sbase + aoff[mt] + kboff);
#pragma unroll
            for (int np = 0; np < 4; np++)
                LDSM4(bf[2 * np][0], bf[2 * np][1], bf[2 * np + 1][0], bf[2 * np + 1][1],
                      sbase + boff[np] + kboff);
#pragma unroll
            for (int mt = 0; mt < 4; mt++)
#pragma unroll
                for (int nt = 0; nt < 8; nt++)
                    mma_f16(acc[mt][nt], af[mt], bf[nt]);
        }
        __syncthreads();
    }

    // ---- epilogue ----
    if (MODE == 2) {
        __half* Cz = (__half*)Cv + (long)bz * sC;
        __half* stage = smem;                    // [128][264] halves (n x m)
#pragma unroll
        for (int mt = 0; mt < 4; mt++) {
            const int r0 = wm * 64 + mt * 16 + g;
#pragma unroll
            for (int nt = 0; nt < 8; nt++) {
                const int c0 = wn * 64 + nt * 8 + t * 2;
                stage[(c0    ) * 264 + r0    ] = __float2half_rn(acc[mt][nt][0]);
                stage[(c0 + 1) * 264 + r0    ] = __float2half_rn(acc[mt][nt][1]);
                stage[(c0    ) * 264 + r0 + 8] = __float2half_rn(acc[mt][nt][2]);
                stage[(c0 + 1) * 264 + r0 + 8] = __float2half_rn(acc[mt][nt][3]);
            }
        }
        __syncthreads();
        const int b2 = m0 >> 10, mq = tid & 63, rq = tid >> 6;
        const int mloc = (m0 & 1023) + mq * 4;
#pragma unroll
        for (int it = 0; it < 32; it++) {
            const int nr = rq + it * 4;
            uint2 v = *(const uint2*)&stage[nr * 264 + mq * 4];
            *(uint2*)&Cz[(long)b2 * foldT + (long)(n0 + nr) * ldT + mloc] = v;
        }
        return;
    }

    const int ldc = gridDim.x * BN;
#pragma unroll
    for (int mt = 0; mt < 4; mt++) {
        const int r0 = m0 + wm * 64 + mt * 16 + g;
#pragma unroll
        for (int nt = 0; nt < 8; nt++) {
            const int c0 = n0 + wn * 64 + nt * 8 + t * 2;
            float2 v0 = { acc[mt][nt][0], acc[mt][nt][1] };
            float2 v1 = { acc[mt][nt][2], acc[mt][nt][3] };
            if (MODE == 0) {
                if (bias) {
                    v0.x += bias[c0]; v0.y += bias[c0 + 1];
                    v1.x += bias[c0]; v1.y += bias[c0 + 1];
                }
                if (OUT_HALF) {
                    __half* Cg = (__half*)Cv + (long)bz * sC;
                    *(__half2*)&Cg[(long)r0 * ldc + c0]       = __floats2half2_rn(v0.x, v0.y);
                    *(__half2*)&Cg[(long)(r0 + 8) * ldc + c0] = __floats2half2_rn(v1.x, v1.y);
                    continue;
                }
            } else { // MODE 1
                const int* mk = mask + (long)bz * SK;
                float p0 = mk[c0] ? -1e9f : 0.f, p1 = mk[c0 + 1] ? -1e9f : 0.f;
                v0.x = v0.x * scale + p0; v0.y = v0.y * scale + p1;
                v1.x = v1.x * scale + p0; v1.y = v1.y * scale + p1;
            }
            float* Cg = (float*)Cv + (long)bz * sC;
            *(float2*)&Cg[(long)r0 * ldc + c0]       = v0;
            *(float2*)&Cg[(long)(r0 + 8) * ldc + c0] = v1;
        }
    }
}

// ================================================================================
// helper kernels
// ================================================================================
// dual convert: grid.y selects tensor (merges Q and K converts into one launch)
__global__ void f32_to_f16_2(const float* __restrict__ a, __half* __restrict__ oa,
                             const float* __restrict__ b, __half* __restrict__ ob) {
    const float* in  = blockIdx.y ? b : a;
    __half*      out = blockIdx.y ? ob : oa;
    long i = ((long)blockIdx.x * 256 + threadIdx.x) * 4;
    float4 v = *(const float4*)&in[i];
    __half2 h0 = __floats2half2_rn(v.x, v.y);
    __half2 h1 = __floats2half2_rn(v.z, v.w);
    uint2 p = { *(uint32_t*)&h0, *(uint32_t*)&h1 };
    *(uint2*)&out[i] = p;
}

__global__ void f32_to_f16(const float* __restrict__ in, __half* __restrict__ out) {
    long i = ((long)blockIdx.x * 256 + threadIdx.x) * 4;
    float4 v = *(const float4*)&in[i];
    __half2 h0 = __floats2half2_rn(v.x, v.y);
    __half2 h1 = __floats2half2_rn(v.z, v.w);
    uint2 p = { *(uint32_t*)&h0, *(uint32_t*)&h1 };
    *(uint2*)&out[i] = p;
}

__global__ void transpose512_2(const float* __restrict__ w0, __half* __restrict__ o0,
                               const float* __restrict__ w1, __half* __restrict__ o1) {
    __shared__ float t[32][33];
    const float* in  = blockIdx.z ? w1 : w0;
    __half*      out = blockIdx.z ? o1 : o0;
    int bx = blockIdx.x * 32, by = blockIdx.y * 32;
    for (int i = threadIdx.y; i < 32; i += 8)
        t[i][threadIdx.x] = in[(by + i) * DM + bx + threadIdx.x];
    __syncthreads();
    for (int i = threadIdx.y; i < 32; i += 8)
        out[(bx + i) * DM + by + threadIdx.x] = __float2half_rn(t[threadIdx.x][i]);
}

__global__ void wl_sumT_tiled(const float* __restrict__ Wl, __half* __restrict__ WleT) {
    __shared__ float t[32][33];
    int bx = blockIdx.x * 32, by = blockIdx.y * 32;   // bx: n, by: k
    for (int i = threadIdx.y; i < 32; i += 8) {
        float s = 0.f;
#pragma unroll
        for (int h = 0; h < NH; h++)
            s += Wl[((long)(h * DM) + by + i) * DM + bx + threadIdx.x];
        t[i][threadIdx.x] = s;
    }
    __syncthreads();
    for (int i = threadIdx.y; i < 32; i += 8)
        WleT[(bx + i) * DM + by + threadIdx.x] = __float2half_rn(t[threadIdx.x][i]);
}

__global__ void bc_kernel(const float* __restrict__ bl, const float* __restrict__ bv,
                          const __half* __restrict__ WleT, float* __restrict__ bc) {
    const int n = blockIdx.x, t = threadIdx.x;
    __shared__ float red[256];
    float s = 0.f;
    for (int k = t; k < DM; k += 256) s += bv[k] * __half2float(WleT[n * DM + k]);
    red[t] = s;
    __syncthreads();
#pragma unroll
    for (int o = 128; o >= 32; o >>= 1) {
        if (t < o) red[t] += red[t + o];
        __syncthreads();
    }
    if (t < 32) {
        float v = red[t];
#pragma unroll
        for (int o = 16; o > 0; o >>= 1)
            v += __shfl_down_sync(0xffffffffu, v, o);
        if (t == 0) bc[n] = bl[n] + v;
    }
}

// sum 4 fp16 split-K partials -> fp16 output
__global__ void reduce4(const __half* __restrict__ p, __half* __restrict__ o) {
    long i = ((long)blockIdx.x * 256 + threadIdx.x) * 4;
    float s[4];
#pragma unroll
    for (int j = 0; j < 4; j++) s[j] = 0.f;
#pragma unroll
    for (int part = 0; part < 4; part++) {
        uint2 v = *(const uint2*)&p[(long)part * DM * DM + i];
        __half2 h0 = *(__half2*)&v.x, h1 = *(__half2*)&v.y;
        s[0] += __low2float(h0);  s[1] += __high2float(h0);
        s[2] += __low2float(h1);  s[3] += __high2float(h1);
    }
    __half2 r0 = __floats2half2_rn(s[0], s[1]);
    __half2 r1 = __floats2half2_rn(s[2], s[3]);
    uint2 r = { *(uint32_t*)&r0, *(uint32_t*)&r1 };
    *(uint2*)&o[i] = r;
}

// fused softmax; writes fp16 probs to att_h (final GEMM A) + fp32 replica 0
__global__ void softmax_head0(const float* __restrict__ att, __half* __restrict__ att_h,
                              float* __restrict__ out_att) {
    const int q = blockIdx.x, b = blockIdx.y, t = threadIdx.x;
    const float* row = att + ((long)(b * SQ + q)) * SK;
    float4 v = ((const float4*)row)[t];

    __shared__ float red[256];
    float m = fmaxf(fmaxf(v.x, v.y), fmaxf(v.z, v.w));
    red[t] = m;
    __syncthreads();
#pragma unroll
    for (int s = 128; s > 0; s >>= 1) {
        if (t < s) red[t] = fmaxf(red[t], red[t + s]);
        __syncthreads();
    }
    m = red[0];
    __syncthreads();

    float4 e;
    e.x = expf(v.x - m); e.y = expf(v.y - m);
    e.z = expf(v.z - m); e.w = expf(v.w - m);
    red[t] = e.x + e.y + e.z + e.w;
    __syncthreads();
#pragma unroll
    for (int s = 128; s > 0; s >>= 1) {
        if (t < s) red[t] += red[t + s];
        __syncthreads();
    }
    float inv = 1.0f / red[0];
    e.x *= inv; e.y *= inv; e.z *= inv; e.w *= inv;

    __half2 h0 = __floats2half2_rn(e.x, e.y);
    __half2 h1 = __floats2half2_rn(e.z, e.w);
    uint2 ph = { *(uint32_t*)&h0, *(uint32_t*)&h1 };
    ((uint2*)(att_h + ((long)(b * SQ + q)) * SK))[t] = ph;

    if (out_att)
        ((float4*)(out_att + (((long)(b * NH) * SQ) + q) * SK))[t] = e;
}

// copy replica 0 -> replicas 1..7 (pure HBM fanout; overlaps final GEMM)
__global__ void replicate7(float* __restrict__ out_att) {
    const int q = blockIdx.x, b = blockIdx.y, t = threadIdx.x;
    const float4* src = (const float4*)(out_att + (((long)(b * NH) * SQ) + q) * SK);
    float4 v = src[t];
#pragma unroll
    for (int h = 1; h < NH; h++)
        ((float4*)(out_att + (((long)(b * NH + h) * SQ) + q) * SK))[t] = v;
}

// ================================================================================
// launch — multi-stream fork/join (graph-capturable via event edges)
// ================================================================================
extern "C" void kernel_launch(void* const* d_in, const int* in_sizes, int n_in,
                              void* d_out, int out_size) {
    const float* Q    = (const float*)d_in[0];
    const float* K    = (const float*)d_in[1];
    const float* V    = (const float*)d_in[2];
    const int*   mask = (const int*)  d_in[3];
    const float* Wq   = (const float*)d_in[4];
    const float* bq   = (const float*)d_in[5];
    const float* Wk   = (const float*)d_in[6];
    const float* bk   = (const float*)d_in[7];
    const float* Wv   = (const float*)d_in[8];
    const float* bv   = (const float*)d_in[9];
    const float* Wl   = (const float*)d_in[10];
    const float* bl   = (const float*)d_in[11];

    __half *Qh, *Kh, *Vh, *Wvh, *Ql, *Kl, *VWt, *att_h, *wleT, *wqT, *wkT, *wcT, *wcP;
    float *att, *bc;
    cudaGetSymbolAddress((void**)&Qh,    g_Qh);
    cudaGetSymbolAddress((void**)&Kh,    g_Kh);
    cudaGetSymbolAddress((void**)&Vh,    g_Vh);
    cudaGetSymbolAddress((void**)&Wvh,   g_Wvh);
    cudaGetSymbolAddress((void**)&Ql,    g_Ql);
    cudaGetSymbolAddress((void**)&Kl,    g_Kl);
    cudaGetSymbolAddress((void**)&VWt,   g_VWt);
    cudaGetSymbolAddress((void**)&att,   g_att);
    cudaGetSymbolAddress((void**)&att_h, g_att_h);
    cudaGetSymbolAddress((void**)&wleT,  g_WleT);
    cudaGetSymbolAddress((void**)&wqT,   g_WqT);
    cudaGetSymbolAddress((void**)&wkT,   g_WkT);
    cudaGetSymbolAddress((void**)&wcT,   g_WcT);
    cudaGetSymbolAddress((void**)&wcP,   g_WcP);
    cudaGetSymbolAddress((void**)&bc,    g_bc);

    float* Yout = (float*)d_out;
    const long YSIZE = (long)BATCH * SQ * DM;
    const long ASIZE = (long)BATCH * NH * SQ * SK;
    float* out_att = ((long)out_size >= YSIZE + ASIZE) ? (Yout + YSIZE) : nullptr;
    const float inv_scale = 1.0f / sqrtf((float)DM);

    cudaFuncSetAttribute(gemm_h<0,0>, cudaFuncAttributeMaxDynamicSharedMemorySize, GEMM_SMEM);
    cudaFuncSetAttribute(gemm_h<0,1>, cudaFuncAttributeMaxDynamicSharedMemorySize, GEMM_SMEM);
    cudaFuncSetAttribute(gemm_h<1,0>, cudaFuncAttributeMaxDynamicSharedMemorySize, GEMM_SMEM);
    cudaFuncSetAttribute(gemm_h<2,1>, cudaFuncAttributeMaxDynamicSharedMemorySize, GEMM_SMEM);

    // lazily-created side streams + events (capture-safe; no device allocs)
    static cudaStream_t sA = nullptr, sB = nullptr;
    static cudaEvent_t  e0 = nullptr, eA = nullptr, eS = nullptr, eB = nullptr;
    if (!sA) {
        cudaStreamCreateWithFlags(&sA, cudaStreamNonBlocking);
        cudaStreamCreateWithFlags(&sB, cudaStreamNonBlocking);
        cudaEventCreateWithFlags(&e0, cudaEventDisableTiming);
        cudaEventCreateWithFlags(&eA, cudaEventDisableTiming);
        cudaEventCreateWithFlags(&eS, cudaEventDisableTiming);
        cudaEventCreateWithFlags(&eB, cudaEventDisableTiming);
    }
    const bool streams_ok = (sA && sB && e0 && eA && eS && eB);
    cudaStream_t wA = streams_ok ? sA : (cudaStream_t)0;   // weight-prep leg
    cudaStream_t wB = streams_ok ? sB : (cudaStream_t)0;   // replicate leg

    const int NBIG = (BATCH * SQ * DM) / 1024;             // blocks for big converts
    const int NSML = (DM * DM) / 1024;

    // ---- fork weight-prep leg ----
    if (streams_ok) {
        cudaEventRecord(e0, 0);
        cudaStreamWaitEvent(wA, e0, 0);
    }
    f32_to_f16<<<NBIG, 256, 0, wA>>>(V, Vh);
    f32_to_f16<<<NSML, 256, 0, wA>>>(Wv, Wvh);
    wl_sumT_tiled<<<dim3(16, 16), dim3(32, 8), 0, wA>>>(Wl, wleT);
    bc_kernel<<<DM, 256, 0, wA>>>(bl, bv, wleT, bc);
    gemm_h<2,1><<<dim3(DM / BN, DM / BM, 4), 256, GEMM_SMEM, wA>>>(
        Wvh, wleT, wcP, 128, 128, 128, (long)DM * DM,
        nullptr, nullptr, 0.f, DM, 0, DM, DM);
    reduce4<<<DM * DM / 1024, 256, 0, wA>>>(wcP, wcT);
    gemm_h<2,1><<<dim3(DM / BN, (BATCH * SK) / BM, 1), 256, GEMM_SMEM, wA>>>(
        Vh, wcT, VWt, DM, 0, 0, 0, nullptr, nullptr, 0.f, SK, (long)DM * SK, DM, DM);
    if (streams_ok) cudaEventRecord(eA, wA);

    // ---- main leg: convert -> Q/K projections -> scores -> softmax ----
    f32_to_f16_2<<<dim3(NBIG, 2), 256>>>(Q, Qh, K, Kh);
    transpose512_2<<<dim3(16, 16, 2), dim3(32, 8)>>>(Wq, wqT, Wk, wkT);
    gemm_h<0,1><<<dim3(DM / BN, (BATCH * SQ) / BM, 1), 256, GEMM_SMEM>>>(
        Qh, wqT, Ql, DM, 0, 0, 0, bq, nullptr, 0.f, 0, 0, DM, DM);
    gemm_h<0,1><<<dim3(DM / BN, (BATCH * SK) / BM, 1), 256, GEMM_SMEM>>>(
        Kh, wkT, Kl, DM, 0, 0, 0, bk, nullptr, 0.f, 0, 0, DM, DM);
    gemm_h<1,0><<<dim3(SK / BN, SQ / BM, BATCH), 256, GEMM_SMEM>>>(
        Ql, Kl, att, DM, (long)SQ * DM, (long)SK * DM, (long)SQ * SK,
        nullptr, mask, inv_scale, 0, 0, DM, DM);
    softmax_head0<<<dim3(SQ, BATCH), 256>>>(att, att_h, out_att);

    // ---- fork replicate leg (final GEMM reads fp16 att_h, not replicas) ----
    if (out_att) {
        if (streams_ok) {
            cudaEventRecord(eS, 0);
            cudaStreamWaitEvent(wB, eS, 0);
        }
        replicate7<<<dim3(SQ, BATCH), 256, 0, wB>>>(out_att);
        if (streams_ok) cudaEventRecord(eB, wB);
    }

    // ---- join weight-prep; final GEMM ----
    if (streams_ok) cudaStreamWaitEvent(0, eA, 0);
    gemm_h<0,0><<<dim3(DM / BN, SQ / BM, BATCH), 256, GEMM_SMEM>>>(
        att_h, VWt, Yout, SK, (long)SQ * SK, (long)DM * SK, (long)SQ * DM,
        bc, nullptr, 0.f, 0, 0, SK, SK);

    // ---- join replicate leg ----
    if (out_att && streams_ok) cudaStreamWaitEvent(0, eB, 0);
}

// round 11
// speedup vs baseline: 1.9920x; 1.0300x over previous
#include <cuda_runtime.h>
#include <cuda_fp16.h>
#include <math.h>
#include <stdint.h>

// Problem constants
#define BATCH 8
#define SQ    1024
#define SK    1024
#define DM    512
#define NH    8

// ---------------- device scratch ----------------------------------------------
__device__ __half g_Qh[BATCH * SQ * DM];
__device__ __half g_Kh[BATCH * SK * DM];
__device__ __half g_Vh[BATCH * SK * DM];
__device__ __half g_Wqh[DM * DM];
__device__ __half g_Wkh[DM * DM];
__device__ __half g_Wvh[DM * DM];
__device__ __half g_M[DM * DM];              // M~ = Wq @ Wk^T (fp16)
__device__ __half g_Km[BATCH * SK * DM];     // K @ M~^T per batch
__device__ __half g_VWt[BATCH * DM * SK];    // (V @ Wc)^T per batch: [b][d][sk]
__device__ float  g_att[BATCH * SQ * SK];    // fp32 scores
__device__ __half g_att_h[BATCH * SQ * SK];  // fp16 probs (final GEMM A)
__device__ __half g_WleT[DM * DM];
__device__ __half g_WcT[DM * DM];
__device__ __half g_WcP[4 * DM * DM];        // shared split-K partials (M~ then WcT)
__device__ float  g_bc[DM];
__device__ float  g_wqbk[DM];
__device__ float  g_wkbq[DM];
__device__ float  g_a[BATCH * SQ];           // row bias for scores
__device__ float  g_b[BATCH * SK];           // col bias for scores
__device__ float  g_c[1];
__device__ float  g_zero = 0.f;              // never written

// ---------------- PTX helpers --------------------------------------------------
__device__ __forceinline__ uint32_t smem_u32(const void* p) {
    uint32_t a;
    asm("{ .reg .u64 t; cvta.to.shared.u64 t, %1; cvt.u32.u64 %0, t; }" : "=r"(a) : "l"(p));
    return a;
}

#define CP_ASYNC16(dst, src) \
    asm volatile("cp.async.cg.shared.global [%0], [%1], 16;" :: "r"(dst), "l"(src) : "memory")
#define CP_COMMIT() asm volatile("cp.async.commit_group;" ::: "memory")
#define CP_WAIT2()  asm volatile("cp.async.wait_group 2;" ::: "memory")
#define CP_WAIT1()  asm volatile("cp.async.wait_group 1;" ::: "memory")
#define CP_WAIT0()  asm volatile("cp.async.wait_group 0;" ::: "memory")

#define LDSM4(r0, r1, r2, r3, addr) \
    asm volatile("ldmatrix.sync.aligned.m8n8.x4.shared.b16 {%0,%1,%2,%3}, [%4];" \
        : "=r"(r0), "=r"(r1), "=r"(r2), "=r"(r3) : "r"(addr))

__device__ __forceinline__ void mma_f16(float* c, const uint32_t* a, const uint32_t* b) {
    asm volatile(
        "mma.sync.aligned.m16n8k16.row.col.f32.f16.f16.f32 "
        "{%0,%1,%2,%3}, {%4,%5,%6,%7}, {%8,%9}, {%0,%1,%2,%3};"
        : "+f"(c[0]), "+f"(c[1]), "+f"(c[2]), "+f"(c[3])
        : "r"(a[0]), "r"(a[1]), "r"(a[2]), "r"(a[3]), "r"(b[0]), "r"(b[1]));
}

// ================================================================================
// fp16 mma.sync GEMM: C[M,N] = A[M,K] @ B[N,K]^T   (fp32 accumulate)
// Block tile 256x128x32, 8 warps (4x2), warp tile 64x64, 3-stage cp.async ring,
// ldmatrix.x4 fragment loads (conflict-free with LDH=40 stride).
// MODE 0: C += bias[n]; output fp16 if OUT_HALF else fp32
// MODE 1: C = C*scale + rowb[bz*SQ+m] + colb[bz*SK+n] + mask[bz][n]*-1e9 (fp32 out)
// MODE 2: transposed fp16 store: out[b2*foldT + n*ldT + mloc]
// grid (N/128, M/256, batches-or-ksplits), 256 threads
// ================================================================================
#define BM 256
#define BN 128
#define BK 32
#define LDH 40
#define A_TILE_H (BM * LDH)                      // 10240
#define B_TILE_H (BN * LDH)                      // 5120
#define STAGE_H  (A_TILE_H + B_TILE_H)           // 15360
#define NSTAGE 3
#define GEMM_SMEM (NSTAGE * STAGE_H * 2)         // 92160 B

template <int MODE, int OUT_HALF>
__global__ void __launch_bounds__(256, 1) gemm_h(
    const __half* __restrict__ A, const __half* __restrict__ B, void* __restrict__ Cv,
    int Kdim, long sA, long sB, long sC,
    const float* __restrict__ bias, const int* __restrict__ mask, float scale,
    int ldT, long foldT, int lda, int ldb,
    const float* __restrict__ rowb, const float* __restrict__ colb)
{
    extern __shared__ __half smem[];
    const uint32_t smb = smem_u32(smem);

    const int tid = threadIdx.x;
    const int lane = tid & 31, wid = tid >> 5;
    const int g = lane >> 2, t = lane & 3;
    const int wm = wid >> 1, wn = wid & 1;       // 4 x 2 warps, warp tile 64x64
    const int m0 = blockIdx.y * BM, n0 = blockIdx.x * BN, bz = blockIdx.z;

    const __half* Ag = A + (long)bz * sA;
    const __half* Bg = B + (long)bz * sB;

    float acc[4][8][4];
#pragma unroll
    for (int i = 0; i < 4; i++)
#pragma unroll
        for (int j = 0; j < 8; j++)
#pragma unroll
            for (int r = 0; r < 4; r++) acc[i][j][r] = 0.f;

    const int NC = Kdim / BK;
    const int lrow = tid >> 2, lchunk = (tid & 3) * 8;   // cp.async slots

    // ldmatrix per-lane base offsets (bytes, relative to stage start)
    const int lj = lane >> 3, lr8 = lane & 7;
    uint32_t aoff[4], boff[4];
#pragma unroll
    for (int mt = 0; mt < 4; mt++)
        aoff[mt] = (uint32_t)(((wm * 64 + mt * 16 + lr8 + 8 * (lj & 1)) * LDH
                               + 8 * (lj >> 1)) * 2);
#pragma unroll
    for (int np = 0; np < 4; np++)
        boff[np] = (uint32_t)((A_TILE_H + (wn * 64 + np * 16 + lr8 + 8 * (lj >> 1)) * LDH
                               + 8 * (lj & 1)) * 2);

    auto issue = [&](int c, int s) {
        const long k0 = (long)c * BK;
        const uint32_t abase = smb + (uint32_t)(s * STAGE_H * 2);
        const uint32_t bbase = abase + (uint32_t)(A_TILE_H * 2);
#pragma unroll
        for (int j = 0; j < 4; j++) {
            int row = lrow + 64 * j;
            CP_ASYNC16(abase + (uint32_t)((row * LDH + lchunk) * 2),
                       Ag + (long)(m0 + row) * lda + k0 + lchunk);
        }
#pragma unroll
        for (int j = 0; j < 2; j++) {
            int row = lrow + 64 * j;
            CP_ASYNC16(bbase + (uint32_t)((row * LDH + lchunk) * 2),
                       Bg + (long)(n0 + row) * ldb + k0 + lchunk);
        }
        CP_COMMIT();
    };

    issue(0, 0);
    if (NC > 1) issue(1, 1);

    for (int c = 0; c < NC; c++) {
        const int buf = c % NSTAGE;
        if (c + 2 < NC) { issue(c + 2, (c + 2) % NSTAGE); CP_WAIT2(); }
        else if (c + 1 < NC) { CP_WAIT1(); }
        else { CP_WAIT0(); }
        __syncthreads();

        const uint32_t sbase = smb + (uint32_t)(buf * STAGE_H * 2);

#pragma unroll
        for (int kk = 0; kk < 2; kk++) {             // two k16 steps per BK=32
            const uint32_t kboff = (uint32_t)(kk * 16 * 2);
            uint32_t af[4][4], bf[8][2];
#pragma unroll
            for (int mt = 0; mt < 4; mt++)
                LDSM4(af[mt][0], af[mt][1], af[mt][2], af[mt][3],
                      sbase + aoff[mt] + kboff);
#pragma unroll
            for (int np = 0; np < 4; np++)
                LDSM4(bf[2 * np][0], bf[2 * np][1], bf[2 * np + 1][0], bf[2 * np + 1][1],
                      sbase + boff[np] + kboff);
#pragma unroll
            for (int mt = 0; mt < 4; mt++)
#pragma unroll
                for (int nt = 0; nt < 8; nt++)
                    mma_f16(acc[mt][nt], af[mt], bf[nt]);
        }
        __syncthreads();
    }

    // ---- epilogue ----
    if (MODE == 2) {
        __half* Cz = (__half*)Cv + (long)bz * sC;
        __half* stage = smem;                    // [128][264] halves (n x m)
#pragma unroll
        for (int mt = 0; mt < 4; mt++) {
            const int r0 = wm * 64 + mt * 16 + g;
#pragma unroll
            for (int nt = 0; nt < 8; nt++) {
                const int c0 = wn * 64 + nt * 8 + t * 2;
                stage[(c0    ) * 264 + r0    ] = __float2half_rn(acc[mt][nt][0]);
                stage[(c0 + 1) * 264 + r0    ] = __float2half_rn(acc[mt][nt][1]);
                stage[(c0    ) * 264 + r0 + 8] = __float2half_rn(acc[mt][nt][2]);
                stage[(c0 + 1) * 264 + r0 + 8] = __float2half_rn(acc[mt][nt][3]);
            }
        }
        __syncthreads();
        const int b2 = m0 >> 10, mq = tid & 63, rq = tid >> 6;
        const int mloc = (m0 & 1023) + mq * 4;
#pragma unroll
        for (int it = 0; it < 32; it++) {
            const int nr = rq + it * 4;
            uint2 v = *(const uint2*)&stage[nr * 264 + mq * 4];
            *(uint2*)&Cz[(long)b2 * foldT + (long)(n0 + nr) * ldT + mloc] = v;
        }
        return;
    }

    const int ldc = gridDim.x * BN;
#pragma unroll
    for (int mt = 0; mt < 4; mt++) {
        const int r0 = m0 + wm * 64 + mt * 16 + g;
#pragma unroll
        for (int nt = 0; nt < 8; nt++) {
            const int c0 = n0 + wn * 64 + nt * 8 + t * 2;
            float2 v0 = { acc[mt][nt][0], acc[mt][nt][1] };
            float2 v1 = { acc[mt][nt][2], acc[mt][nt][3] };
            if (MODE == 0) {
                if (bias) {
                    v0.x += bias[c0]; v0.y += bias[c0 + 1];
                    v1.x += bias[c0]; v1.y += bias[c0 + 1];
                }
                if (OUT_HALF) {
                    __half* Cg = (__half*)Cv + (long)bz * sC;
                    *(__half2*)&Cg[(long)r0 * ldc + c0]       = __floats2half2_rn(v0.x, v0.y);
                    *(__half2*)&Cg[(long)(r0 + 8) * ldc + c0] = __floats2half2_rn(v1.x, v1.y);
                    continue;
                }
            } else { // MODE 1: scale + row/col rank-1 bias + mask
                const int* mk = mask + (long)bz * SK;
                float p0 = mk[c0] ? -1e9f : 0.f, p1 = mk[c0 + 1] ? -1e9f : 0.f;
                float ra  = rowb[(long)bz * SQ + r0];
                float ra8 = rowb[(long)bz * SQ + r0 + 8];
                float cb0 = colb[(long)bz * SK + c0];
                float cb1 = colb[(long)bz * SK + c0 + 1];
                v0.x = v0.x * scale + ra  + cb0 + p0; v0.y = v0.y * scale + ra  + cb1 + p1;
                v1.x = v1.x * scale + ra8 + cb0 + p0; v1.y = v1.y * scale + ra8 + cb1 + p1;
            }
            float* Cg = (float*)Cv + (long)bz * sC;
            *(float2*)&Cg[(long)r0 * ldc + c0]       = v0;
            *(float2*)&Cg[(long)(r0 + 8) * ldc + c0] = v1;
        }
    }
}

// ================================================================================
// helper kernels
// ================================================================================
__global__ void f32_to_f16(const float* __restrict__ in, __half* __restrict__ out) {
    long i = ((long)blockIdx.x * 256 + threadIdx.x) * 4;
    float4 v = *(const float4*)&in[i];
    __half2 h0 = __floats2half2_rn(v.x, v.y);
    __half2 h1 = __floats2half2_rn(v.z, v.w);
    uint2 p = { *(uint32_t*)&h0, *(uint32_t*)&h1 };
    *(uint2*)&out[i] = p;
}

__global__ void wl_sumT_tiled(const float* __restrict__ Wl, __half* __restrict__ WleT) {
    __shared__ float t[32][33];
    int bx = blockIdx.x * 32, by = blockIdx.y * 32;   // bx: n, by: k
    for (int i = threadIdx.y; i < 32; i += 8) {
        float s = 0.f;
#pragma unroll
        for (int h = 0; h < NH; h++)
            s += Wl[((long)(h * DM) + by + i) * DM + bx + threadIdx.x];
        t[i][threadIdx.x] = s;
    }
    __syncthreads();
    for (int i = threadIdx.y; i < 32; i += 8)
        WleT[(bx + i) * DM + by + threadIdx.x] = __float2half_rn(t[threadIdx.x][i]);
}

__global__ void bc_kernel(const float* __restrict__ bl, const float* __restrict__ bv,
                          const __half* __restrict__ WleT, float* __restrict__ bc) {
    const int n = blockIdx.x, t = threadIdx.x;
    __shared__ float red[256];
    float s = 0.f;
    for (int k = t; k < DM; k += 256) s += bv[k] * __half2float(WleT[n * DM + k]);
    red[t] = s;
    __syncthreads();
#pragma unroll
    for (int o = 128; o >= 32; o >>= 1) {
        if (t < o) red[t] += red[t + o];
        __syncthreads();
    }
    if (t < 32) {
        float v = red[t];
#pragma unroll
        for (int o = 16; o > 0; o >>= 1)
            v += __shfl_down_sync(0xffffffffu, v, o);
        if (t == 0) bc[n] = bl[n] + v;
    }
}

// c = dot(a, b) over DM; single block
__global__ void dot512(const float* __restrict__ a, const float* __restrict__ b,
                       float* __restrict__ out) {
    const int t = threadIdx.x;
    __shared__ float red[256];
    float s = 0.f;
    for (int k = t; k < DM; k += 256) s += a[k] * b[k];
    red[t] = s;
    __syncthreads();
#pragma unroll
    for (int o = 128; o >= 32; o >>= 1) {
        if (t < o) red[t] += red[t + o];
        __syncthreads();
    }
    if (t < 32) {
        float v = red[t];
#pragma unroll
        for (int o = 16; o > 0; o >>= 1)
            v += __shfl_down_sync(0xffffffffu, v, o);
        if (t == 0) out[0] = v;
    }
}

// out[f] = dot(W[f,:], v); grid DM blocks
__global__ void vecdot512(const float* __restrict__ W, const float* __restrict__ v,
                          float* __restrict__ out) {
    const int f = blockIdx.x, t = threadIdx.x;
    __shared__ float red[128];
    float s = 0.f;
    for (int k = t; k < DM; k += 128) s += W[(long)f * DM + k] * v[k];
    red[t] = s;
    __syncthreads();
#pragma unroll
    for (int o = 64; o >= 32; o >>= 1) {
        if (t < o) red[t] += red[t + o];
        __syncthreads();
    }
    if (t < 32) {
        float x = red[t];
#pragma unroll
        for (int o = 16; o > 0; o >>= 1)
            x += __shfl_down_sync(0xffffffffu, x, o);
        if (t == 0) out[f] = x;
    }
}

// out[r] = (dot(X[r,:], vec) + cadd[0]) * scale ; grid = rows
__global__ void rowdot(const float* __restrict__ X, const float* __restrict__ vec,
                       const float* __restrict__ cadd, float* __restrict__ out,
                       float scale) {
    const int r = blockIdx.x, t = threadIdx.x;
    __shared__ float red[128];
    float s = 0.f;
    for (int k = t; k < DM; k += 128) s += X[(long)r * DM + k] * vec[k];
    red[t] = s;
    __syncthreads();
#pragma unroll
    for (int o = 64; o >= 32; o >>= 1) {
        if (t < o) red[t] += red[t + o];
        __syncthreads();
    }
    if (t < 32) {
        float x = red[t];
#pragma unroll
        for (int o = 16; o > 0; o >>= 1)
            x += __shfl_down_sync(0xffffffffu, x, o);
        if (t == 0) out[r] = (x + cadd[0]) * scale;
    }
}

// sum 4 fp16 split-K partials -> fp16 output
__global__ void reduce4(const __half* __restrict__ p, __half* __restrict__ o) {
    long i = ((long)blockIdx.x * 256 + threadIdx.x) * 4;
    float s[4];
#pragma unroll
    for (int j = 0; j < 4; j++) s[j] = 0.f;
#pragma unroll
    for (int part = 0; part < 4; part++) {
        uint2 v = *(const uint2*)&p[(long)part * DM * DM + i];
        __half2 h0 = *(__half2*)&v.x, h1 = *(__half2*)&v.y;
        s[0] += __low2float(h0);  s[1] += __high2float(h0);
        s[2] += __low2float(h1);  s[3] += __high2float(h1);
    }
    __half2 r0 = __floats2half2_rn(s[0], s[1]);
    __half2 r1 = __floats2half2_rn(s[2], s[3]);
    uint2 r = { *(uint32_t*)&r0, *(uint32_t*)&r1 };
    *(uint2*)&o[i] = r;
}

// fused softmax; writes fp16 probs to att_h (final GEMM A) + fp32 replica 0
__global__ void softmax_head0(const float* __restrict__ att, __half* __restrict__ att_h,
                              float* __restrict__ out_att) {
    const int q = blockIdx.x, b = blockIdx.y, t = threadIdx.x;
    const float* row = att + ((long)(b * SQ + q)) * SK;
    float4 v = ((const float4*)row)[t];

    __shared__ float red[256];
    float m = fmaxf(fmaxf(v.x, v.y), fmaxf(v.z, v.w));
    red[t] = m;
    __syncthreads();
#pragma unroll
    for (int s = 128; s > 0; s >>= 1) {
        if (t < s) red[t] = fmaxf(red[t], red[t + s]);
        __syncthreads();
    }
    m = red[0];
    __syncthreads();

    float4 e;
    e.x = expf(v.x - m); e.y = expf(v.y - m);
    e.z = expf(v.z - m); e.w = expf(v.w - m);
    red[t] = e.x + e.y + e.z + e.w;
    __syncthreads();
#pragma unroll
    for (int s = 128; s > 0; s >>= 1) {
        if (t < s) red[t] += red[t + s];
        __syncthreads();
    }
    float inv = 1.0f / red[0];
    e.x *= inv; e.y *= inv; e.z *= inv; e.w *= inv;

    __half2 h0 = __floats2half2_rn(e.x, e.y);
    __half2 h1 = __floats2half2_rn(e.z, e.w);
    uint2 ph = { *(uint32_t*)&h0, *(uint32_t*)&h1 };
    ((uint2*)(att_h + ((long)(b * SQ + q)) * SK))[t] = ph;

    if (out_att)
        ((float4*)(out_att + (((long)(b * NH) * SQ) + q) * SK))[t] = e;
}

// copy replica 0 -> replicas 1..7 (pure HBM fanout; overlaps final GEMM)
__global__ void replicate7(float* __restrict__ out_att) {
    const int q = blockIdx.x, b = blockIdx.y, t = threadIdx.x;
    const float4* src = (const float4*)(out_att + (((long)(b * NH) * SQ) + q) * SK);
    float4 v = src[t];
#pragma unroll
    for (int h = 1; h < NH; h++)
        ((float4*)(out_att + (((long)(b * NH + h) * SQ) + q) * SK))[t] = v;
}

// ================================================================================
// launch — multi-stream fork/join (graph-capturable via event edges)
// ================================================================================
extern "C" void kernel_launch(void* const* d_in, const int* in_sizes, int n_in,
                              void* d_out, int out_size) {
    const float* Q    = (const float*)d_in[0];
    const float* K    = (const float*)d_in[1];
    const float* V    = (const float*)d_in[2];
    const int*   mask = (const int*)  d_in[3];
    const float* Wq   = (const float*)d_in[4];
    const float* bq   = (const float*)d_in[5];
    const float* Wk   = (const float*)d_in[6];
    const float* bk   = (const float*)d_in[7];
    const float* Wv   = (const float*)d_in[8];
    const float* bv   = (const float*)d_in[9];
    const float* Wl   = (const float*)d_in[10];
    const float* bl   = (const float*)d_in[11];

    __half *Qh, *Kh, *Vh, *Wqh, *Wkh, *Wvh, *Mh, *Km, *VWt, *att_h, *wleT, *wcT, *wcP;
    float *att, *bc, *wqbk, *wkbq, *av, *bvv, *cs, *zs;
    cudaGetSymbolAddress((void**)&Qh,    g_Qh);
    cudaGetSymbolAddress((void**)&Kh,    g_Kh);
    cudaGetSymbolAddress((void**)&Vh,    g_Vh);
    cudaGetSymbolAddress((void**)&Wqh,   g_Wqh);
    cudaGetSymbolAddress((void**)&Wkh,   g_Wkh);
    cudaGetSymbolAddress((void**)&Wvh,   g_Wvh);
    cudaGetSymbolAddress((void**)&Mh,    g_M);
    cudaGetSymbolAddress((void**)&Km,    g_Km);
    cudaGetSymbolAddress((void**)&VWt,   g_VWt);
    cudaGetSymbolAddress((void**)&att,   g_att);
    cudaGetSymbolAddress((void**)&att_h, g_att_h);
    cudaGetSymbolAddress((void**)&wleT,  g_WleT);
    cudaGetSymbolAddress((void**)&wcT,   g_WcT);
    cudaGetSymbolAddress((void**)&wcP,   g_WcP);
    cudaGetSymbolAddress((void**)&bc,    g_bc);
    cudaGetSymbolAddress((void**)&wqbk,  g_wqbk);
    cudaGetSymbolAddress((void**)&wkbq,  g_wkbq);
    cudaGetSymbolAddress((void**)&av,    g_a);
    cudaGetSymbolAddress((void**)&bvv,   g_b);
    cudaGetSymbolAddress((void**)&cs,    g_c);
    cudaGetSymbolAddress((void**)&zs,    g_zero);

    float* Yout = (float*)d_out;
    const long YSIZE = (long)BATCH * SQ * DM;
    const long ASIZE = (long)BATCH * NH * SQ * SK;
    float* out_att = ((long)out_size >= YSIZE + ASIZE) ? (Yout + YSIZE) : nullptr;
    const float inv_scale = 1.0f / sqrtf((float)DM);

    cudaFuncSetAttribute(gemm_h<0,0>, cudaFuncAttributeMaxDynamicSharedMemorySize, GEMM_SMEM);
    cudaFuncSetAttribute(gemm_h<0,1>, cudaFuncAttributeMaxDynamicSharedMemorySize, GEMM_SMEM);
    cudaFuncSetAttribute(gemm_h<1,0>, cudaFuncAttributeMaxDynamicSharedMemorySize, GEMM_SMEM);
    cudaFuncSetAttribute(gemm_h<2,1>, cudaFuncAttributeMaxDynamicSharedMemorySize, GEMM_SMEM);

    // lazily-created side streams + events (capture-safe; no device allocs)
    static cudaStream_t sA = nullptr, sB = nullptr;
    static cudaEvent_t  e0 = nullptr, eV = nullptr, eK = nullptr,
                        eA = nullptr, eS = nullptr, eB = nullptr;
    if (!sA) {
        cudaStreamCreateWithFlags(&sA, cudaStreamNonBlocking);
        cudaStreamCreateWithFlags(&sB, cudaStreamNonBlocking);
        cudaEventCreateWithFlags(&e0, cudaEventDisableTiming);
        cudaEventCreateWithFlags(&eV, cudaEventDisableTiming);
        cudaEventCreateWithFlags(&eK, cudaEventDisableTiming);
        cudaEventCreateWithFlags(&eA, cudaEventDisableTiming);
        cudaEventCreateWithFlags(&eS, cudaEventDisableTiming);
        cudaEventCreateWithFlags(&eB, cudaEventDisableTiming);
    }
    const bool streams_ok = (sA && sB && e0 && eV && eK && eA && eS && eB);
    cudaStream_t wA = streams_ok ? sA : (cudaStream_t)0;   // weight/K leg
    cudaStream_t wB = streams_ok ? sB : (cudaStream_t)0;   // replicate leg

    const int NBIG = (BATCH * SQ * DM) / 1024;
    const int NSML = (DM * DM) / 1024;

    // ---- fork side leg A ----
    if (streams_ok) {
        cudaEventRecord(e0, 0);
        cudaStreamWaitEvent(wA, e0, 0);
    }
    // critical prefix: K path for scores
    f32_to_f16<<<NSML, 256, 0, wA>>>(Wq, Wqh);
    f32_to_f16<<<NSML, 256, 0, wA>>>(Wk, Wkh);
    f32_to_f16<<<NBIG, 256, 0, wA>>>(K, Kh);
    dot512<<<1, 256, 0, wA>>>(bq, bk, cs);
    vecdot512<<<DM, 128, 0, wA>>>(Wq, bk, wqbk);
    vecdot512<<<DM, 128, 0, wA>>>(Wk, bq, wkbq);
    if (streams_ok) cudaEventRecord(eV, wA);
    // M~ = Wq @ Wk^T via split-K, then Km = Kh @ M~^T
    gemm_h<0,1><<<dim3(DM / BN, DM / BM, 4), 256, GEMM_SMEM, wA>>>(
        Wqh, Wkh, wcP, 128, 128, 128, (long)DM * DM,
        nullptr, nullptr, 0.f, 0, 0, DM, DM, nullptr, nullptr);
    reduce4<<<DM * DM / 1024, 256, 0, wA>>>(wcP, Mh);
    gemm_h<0,1><<<dim3(DM / BN, (BATCH * SK) / BM, 1), 256, GEMM_SMEM, wA>>>(
        Kh, Mh, Km, DM, 0, 0, 0, nullptr, nullptr, 0.f, 0, 0, DM, DM, nullptr, nullptr);
    if (streams_ok) cudaEventRecord(eK, wA);
    // V / output-projection path
    f32_to_f16<<<NBIG, 256, 0, wA>>>(V, Vh);
    f32_to_f16<<<NSML, 256, 0, wA>>>(Wv, Wvh);
    wl_sumT_tiled<<<dim3(16, 16), dim3(32, 8), 0, wA>>>(Wl, wleT);
    bc_kernel<<<DM, 256, 0, wA>>>(bl, bv, wleT, bc);
    gemm_h<2,1><<<dim3(DM / BN, DM / BM, 4), 256, GEMM_SMEM, wA>>>(
        Wvh, wleT, wcP, 128, 128, 128, (long)DM * DM,
        nullptr, nullptr, 0.f, DM, 0, DM, DM, nullptr, nullptr);
    reduce4<<<DM * DM / 1024, 256, 0, wA>>>(wcP, wcT);
    gemm_h<2,1><<<dim3(DM / BN, (BATCH * SK) / BM, 1), 256, GEMM_SMEM, wA>>>(
        Vh, wcT, VWt, DM, 0, 0, 0, nullptr, nullptr, 0.f, SK, (long)DM * SK, DM, DM,
        nullptr, nullptr);
    if (streams_ok) cudaEventRecord(eA, wA);

    // ---- main leg: Q convert + rank-1 bias vectors (overlap leg A) ----
    f32_to_f16<<<NBIG, 256>>>(Q, Qh);
    if (streams_ok) cudaStreamWaitEvent(0, eV, 0);
    rowdot<<<BATCH * SQ, 128>>>(Q, wqbk, cs, av, inv_scale);
    rowdot<<<BATCH * SK, 128>>>(K, wkbq, zs, bvv, inv_scale);

    // ---- scores = Qh @ Km^T * s + a + b + mask ----
    if (streams_ok) cudaStreamWaitEvent(0, eK, 0);
    gemm_h<1,0><<<dim3(SK / BN, SQ / BM, BATCH), 256, GEMM_SMEM>>>(
        Qh, Km, att, DM, (long)SQ * DM, (long)SK * DM, (long)SQ * SK,
        nullptr, mask, inv_scale, 0, 0, DM, DM, av, bvv);
    softmax_head0<<<dim3(SQ, BATCH), 256>>>(att, att_h, out_att);

    // ---- fork replicate leg ----
    if (out_att) {
        if (streams_ok) {
            cudaEventRecord(eS, 0);
            cudaStreamWaitEvent(wB, eS, 0);
        }
        replicate7<<<dim3(SQ, BATCH), 256, 0, wB>>>(out_att);
        if (streams_ok) cudaEventRecord(eB, wB);
    }

    // ---- join leg A; final GEMM ----
    if (streams_ok) cudaStreamWaitEvent(0, eA, 0);
    gemm_h<0,0><<<dim3(DM / BN, SQ / BM, BATCH), 256, GEMM_SMEM>>>(
        att_h, VWt, Yout, SK, (long)SQ * SK, (long)DM * SK, (long)SQ * DM,
        bc, nullptr, 0.f, 0, 0, SK, SK, nullptr, nullptr);

    // ---- join replicate leg ----
    if (out_att && streams_ok) cudaStreamWaitEvent(0, eB, 0);
}